// round 13
// baseline (speedup 1.0000x reference)
#include <cuda_runtime.h>
#include <cuda_bf16.h>
#include <mma.h>
#include <math.h>

using namespace nvcuda;

// Problem constants
constexpr int Bc   = 2;
constexpr int Tc   = 2048;
constexpr int Dc   = 2048;
constexpr int Hc   = 32;
constexpr int HKVc = 8;
constexpr int DHc  = 64;
constexpr int BT   = Bc * Tc;          // 4096
constexpr int DKV  = HKVc * DHc;       // 512

// ---------------- scratch (__device__ globals, no allocation) ----------------
// NOTE: only ever referenced from DEVICE code (never passed from host).
__device__ float g_qraw[BT * Dc];
__device__ float g_kraw[BT * DKV];
__device__ float g_vraw[BT * DKV];

// pre-split bf16 hi/lo operand buffers
__device__ __nv_bfloat16 g_xh [BT * Dc],  g_xl [BT * Dc];
__device__ __nv_bfloat16 g_wqh[Dc * Dc],  g_wql[Dc * Dc];
__device__ __nv_bfloat16 g_wkh[Dc * DKV], g_wkl[Dc * DKV];
__device__ __nv_bfloat16 g_wvh[Dc * DKV], g_wvl[Dc * DKV];
__device__ __nv_bfloat16 g_woh[Dc * Dc],  g_wol[Dc * Dc];
__device__ __nv_bfloat16 g_qh [BT * Dc],  g_ql [BT * Dc];   // [B,H,T,DH] roped
__device__ __nv_bfloat16 g_kh [BT * DKV], g_kl [BT * DKV];  // [B,HKV,T,DH] roped
__device__ __nv_bfloat16 g_vh [BT * DKV], g_vl [BT * DKV];  // [B,HKV,T,DH]
__device__ __nv_bfloat16 g_ctxh[BT * Dc], g_ctxl[BT * Dc];  // attention out hi/lo

// RoPE tables: [T][32]
__device__ float g_rc[Tc * 32], g_rs[Tc * 32];

// ---------------- helpers -----------------------------------------------------
__device__ __forceinline__ void split4(const float4 v,
                                       __nv_bfloat16* hi, __nv_bfloat16* lo) {
    const __nv_bfloat16 hx = __float2bfloat16_rn(v.x);
    const __nv_bfloat16 hy = __float2bfloat16_rn(v.y);
    const __nv_bfloat16 hz = __float2bfloat16_rn(v.z);
    const __nv_bfloat16 hw = __float2bfloat16_rn(v.w);
    __nv_bfloat162* h2 = reinterpret_cast<__nv_bfloat162*>(hi);
    __nv_bfloat162* l2 = reinterpret_cast<__nv_bfloat162*>(lo);
    h2[0] = __halves2bfloat162(hx, hy);
    h2[1] = __halves2bfloat162(hz, hw);
    l2[0] = __halves2bfloat162(__float2bfloat16_rn(v.x - __bfloat162float(hx)),
                               __float2bfloat16_rn(v.y - __bfloat162float(hy)));
    l2[1] = __halves2bfloat162(__float2bfloat16_rn(v.z - __bfloat162float(hz)),
                               __float2bfloat16_rn(v.w - __bfloat162float(hw)));
}

// ---------------- elementwise split kernels -----------------------------------
__global__ __launch_bounds__(256) void k_split_x(const float* __restrict__ src) {
    const int i = blockIdx.x * 256 + threadIdx.x;
    const float4 v = reinterpret_cast<const float4*>(src)[i];
    split4(v, g_xh + (size_t)i * 4, g_xl + (size_t)i * 4);
}
__global__ __launch_bounds__(256) void k_split_wq(const float* __restrict__ src) {
    const int i = blockIdx.x * 256 + threadIdx.x;
    const float4 v = reinterpret_cast<const float4*>(src)[i];
    split4(v, g_wqh + (size_t)i * 4, g_wql + (size_t)i * 4);
}
__global__ __launch_bounds__(256) void k_split_wk(const float* __restrict__ src) {
    const int i = blockIdx.x * 256 + threadIdx.x;
    const float4 v = reinterpret_cast<const float4*>(src)[i];
    split4(v, g_wkh + (size_t)i * 4, g_wkl + (size_t)i * 4);
}
__global__ __launch_bounds__(256) void k_split_wv(const float* __restrict__ src) {
    const int i = blockIdx.x * 256 + threadIdx.x;
    const float4 v = reinterpret_cast<const float4*>(src)[i];
    split4(v, g_wvh + (size_t)i * 4, g_wvl + (size_t)i * 4);
}
__global__ __launch_bounds__(256) void k_split_wo(const float* __restrict__ src) {
    const int i = blockIdx.x * 256 + threadIdx.x;
    const float4 v = reinterpret_cast<const float4*>(src)[i];
    split4(v, g_woh + (size_t)i * 4, g_wol + (size_t)i * 4);
}
// V: [B,T,HKV*DH] -> [B,HKV,T,DH], split to hi/lo
__global__ __launch_bounds__(256) void k_split_v() {
    const int i4 = blockIdx.x * 256 + threadIdx.x;   // over BT*DKV/4
    const int e  = i4 * 4;
    const int d  = e & 63;
    const int t  = (e >> 6) & 2047;
    const int kv = (e >> 17) & 7;
    const int b  = e >> 20;
    const float4 v = *reinterpret_cast<const float4*>(
        g_vraw + (size_t)(b * Tc + t) * DKV + kv * DHc + d);
    split4(v, g_vh + e, g_vl + e);
}

// ---------------- RoPE table ---------------------------------------------------
#define ROPE_LN_C 0.28782313662425575f

__global__ __launch_bounds__(256) void k_rope_table() {
    const int idx = blockIdx.x * 256 + threadIdx.x;   // over Tc*32
    const int t = idx >> 5;
    const int i = idx & 31;
    const float ang = (float)t * expf(-(float)i * ROPE_LN_C);
    g_rc[idx] = cosf(ang);
    g_rs[idx] = sinf(ang);
}

// ---------------- pure bf16 GEMM via wmma (R9 body: BK=32, 1 sync/tile) ------
// C[4096, N] = (Ah+Al)[4096, 2048] @ (Bh+Bl)[2048, N]  (bf16x3: drops Al*Bl)
// block = 256 (8 warps: 4 along M x 2 along N), CTA tile 128x128, BK=32.
template <int N>
__device__ __forceinline__ void bf16_gemm_body(const __nv_bfloat16* __restrict__ Ahg,
                                               const __nv_bfloat16* __restrict__ Alg,
                                               const __nv_bfloat16* __restrict__ Bhg,
                                               const __nv_bfloat16* __restrict__ Blg,
                                               float* __restrict__ C) {
    constexpr int K  = 2048;
    constexpr int BM = 128, BN = 128, BK = 32;
    constexpr int ASTR = BK + 8;   // 40 bf16 = 80 B per row
    constexpr int BSTR = BN + 8;   // 136 bf16 = 272 B per row

    __shared__ __align__(32) __nv_bfloat16 Ah[BM][ASTR];
    __shared__ __align__(32) __nv_bfloat16 Al[BM][ASTR];
    __shared__ __align__(32) __nv_bfloat16 Bh[BK][BSTR];
    __shared__ __align__(32) __nv_bfloat16 Bl[BK][BSTR];

    const int tid  = threadIdx.x;
    const int warp = tid >> 5;
    const int wm   = (warp >> 1) * 32;
    const int wn   = (warp & 1) * 64;
    const int brow = blockIdx.y * BM;
    const int bcol = blockIdx.x * BN;

    const int ar0 = tid >> 2;              // A row of first vec (0..63)
    const int ac  = (tid & 3) * 8;         // A col (bf16 units)
    const int br0 = tid >> 4;              // B row of first vec (0..15)
    const int bc  = (tid & 15) * 8;

    wmma::fragment<wmma::accumulator, 16, 16, 16, float> acc[2][4];
#pragma unroll
    for (int mi = 0; mi < 2; mi++) {
#pragma unroll
        for (int nj = 0; nj < 4; nj++) {
            wmma::fill_fragment(acc[mi][nj], 0.0f);
        }
    }

    uint4 ahR[2], alR[2], bhR[2], blR[2];
    // load tile 0
#pragma unroll
    for (int j = 0; j < 2; j++) {
        const size_t aoff = (size_t)(brow + ar0 + j * 64) * K + ac;
        ahR[j] = *reinterpret_cast<const uint4*>(Ahg + aoff);
        alR[j] = *reinterpret_cast<const uint4*>(Alg + aoff);
        const size_t boff = (size_t)(br0 + j * 16) * N + bcol + bc;
        bhR[j] = *reinterpret_cast<const uint4*>(Bhg + boff);
        blR[j] = *reinterpret_cast<const uint4*>(Blg + boff);
    }
    // store tile 0
#pragma unroll
    for (int j = 0; j < 2; j++) {
        *reinterpret_cast<uint4*>(&Ah[ar0 + j * 64][ac]) = ahR[j];
        *reinterpret_cast<uint4*>(&Al[ar0 + j * 64][ac]) = alR[j];
        *reinterpret_cast<uint4*>(&Bh[br0 + j * 16][bc]) = bhR[j];
        *reinterpret_cast<uint4*>(&Bl[br0 + j * 16][bc]) = blR[j];
    }

    for (int kt = 0; kt < K / BK; kt++) {
        __syncthreads();

        // issue global loads for next tile
        if (kt + 1 < K / BK) {
            const int k0 = (kt + 1) * BK;
#pragma unroll
            for (int j = 0; j < 2; j++) {
                const size_t aoff = (size_t)(brow + ar0 + j * 64) * K + k0 + ac;
                ahR[j] = *reinterpret_cast<const uint4*>(Ahg + aoff);
                alR[j] = *reinterpret_cast<const uint4*>(Alg + aoff);
                const size_t boff = (size_t)(k0 + br0 + j * 16) * N + bcol + bc;
                bhR[j] = *reinterpret_cast<const uint4*>(Bhg + boff);
                blR[j] = *reinterpret_cast<const uint4*>(Blg + boff);
            }
        }

#pragma unroll
        for (int ks = 0; ks < 2; ks++) {
            wmma::fragment<wmma::matrix_a, 16, 16, 16, __nv_bfloat16, wmma::row_major> fAh[2];
            wmma::fragment<wmma::matrix_a, 16, 16, 16, __nv_bfloat16, wmma::row_major> fAl[2];
#pragma unroll
            for (int mi = 0; mi < 2; mi++) {
                wmma::load_matrix_sync(fAh[mi], &Ah[wm + mi * 16][ks * 16], ASTR);
                wmma::load_matrix_sync(fAl[mi], &Al[wm + mi * 16][ks * 16], ASTR);
            }
#pragma unroll
            for (int nj = 0; nj < 4; nj++) {
                wmma::fragment<wmma::matrix_b, 16, 16, 16, __nv_bfloat16, wmma::row_major> fBh;
                wmma::fragment<wmma::matrix_b, 16, 16, 16, __nv_bfloat16, wmma::row_major> fBl;
                wmma::load_matrix_sync(fBh, &Bh[ks * 16][wn + nj * 16], BSTR);
                wmma::load_matrix_sync(fBl, &Bl[ks * 16][wn + nj * 16], BSTR);
#pragma unroll
                for (int mi = 0; mi < 2; mi++) {
                    wmma::mma_sync(acc[mi][nj], fAh[mi], fBh, acc[mi][nj]);
                    wmma::mma_sync(acc[mi][nj], fAh[mi], fBl, acc[mi][nj]);
                    wmma::mma_sync(acc[mi][nj], fAl[mi], fBh, acc[mi][nj]);
                }
            }
        }

        // store next tile after compute; next loop-top sync protects readers
        if (kt + 1 < K / BK) {
            __syncthreads();
#pragma unroll
            for (int j = 0; j < 2; j++) {
                *reinterpret_cast<uint4*>(&Ah[ar0 + j * 64][ac]) = ahR[j];
                *reinterpret_cast<uint4*>(&Al[ar0 + j * 64][ac]) = alR[j];
                *reinterpret_cast<uint4*>(&Bh[br0 + j * 16][bc]) = bhR[j];
                *reinterpret_cast<uint4*>(&Bl[br0 + j * 16][bc]) = blR[j];
            }
        }
    }

#pragma unroll
    for (int mi = 0; mi < 2; mi++) {
#pragma unroll
        for (int nj = 0; nj < 4; nj++) {
            float* p = C + (size_t)(brow + wm + mi * 16) * N + bcol + wn + nj * 16;
            wmma::store_matrix_sync(p, acc[mi][nj], N, wmma::mem_row_major);
        }
    }
}

// Wrappers: scratch globals referenced from DEVICE code only.
__global__ __launch_bounds__(256) void k_qproj() {
    bf16_gemm_body<Dc>(g_xh, g_xl, g_wqh, g_wql, g_qraw);
}
__global__ __launch_bounds__(256) void k_kproj() {
    bf16_gemm_body<DKV>(g_xh, g_xl, g_wkh, g_wkl, g_kraw);
}
__global__ __launch_bounds__(256) void k_vproj() {
    bf16_gemm_body<DKV>(g_xh, g_xl, g_wvh, g_wvl, g_vraw);
}
__global__ __launch_bounds__(256) void k_oproj(float* __restrict__ out) {
    bf16_gemm_body<Dc>(g_ctxh, g_ctxl, g_woh, g_wol, out);
}

// ---------------- RoPE (table lookup, fused hi/lo split output) ---------------
__global__ __launch_bounds__(256) void rope_q_kernel() {
    const int idx = blockIdx.x * 256 + threadIdx.x;   // over [B,H,T,DH]
    const int d = idx & 63;
    const int t = (idx >> 6) & 2047;
    const int h = (idx >> 17) & 31;
    const int b = idx >> 22;
    const size_t row = (size_t)(b * Tc + t) * Dc + h * DHc;
    const float raw  = g_qraw[row + d];
    const float pair = g_qraw[row + ((d < 32) ? d + 32 : d - 32)];
    const float rot  = (d < 32) ? -pair : pair;
    const int   ti   = t * 32 + (d & 31);
    const float val  = raw * g_rc[ti] + rot * g_rs[ti];
    const __nv_bfloat16 hi = __float2bfloat16_rn(val);
    g_qh[idx] = hi;
    g_ql[idx] = __float2bfloat16_rn(val - __bfloat162float(hi));
}

__global__ __launch_bounds__(256) void rope_k_kernel() {
    const int idx = blockIdx.x * 256 + threadIdx.x;   // over [B,HKV,T,DH]
    const int d  = idx & 63;
    const int t  = (idx >> 6) & 2047;
    const int kv = (idx >> 17) & 7;
    const int b  = idx >> 20;
    const size_t row = (size_t)(b * Tc + t) * DKV + kv * DHc;
    const float raw  = g_kraw[row + d];
    const float pair = g_kraw[row + ((d < 32) ? d + 32 : d - 32)];
    const float rot  = (d < 32) ? -pair : pair;
    const int   ti   = t * 32 + (d & 31);
    const float val  = raw * g_rc[ti] + rot * g_rs[ti];
    const __nv_bfloat16 hi = __float2bfloat16_rn(val);
    g_kh[idx] = hi;
    g_kl[idx] = __float2bfloat16_rn(val - __bfloat162float(hi));
}

// ---------------- Causal flash attention (bf16x3 wmma, parallel softmax) -----
// grid: (T/64, H, B), block: 256 (8 warps: 4 along q x 2 along key/dh)
__global__ __launch_bounds__(256) void attn_kernel() {
    constexpr int BQ  = 64;
    constexpr int BKT = 32;
    constexpr int KP  = 72;   // bf16 row stride for K/V/Q-staging
    constexpr int PP  = 40;   // bf16 row stride for P
    constexpr int OP  = 72;   // fp32 row stride for Ss/Os

    __shared__ __align__(32) __nv_bfloat16 Kh[BKT][KP];
    __shared__ __align__(32) __nv_bfloat16 Kl[BKT][KP];
    __shared__ __align__(32) __nv_bfloat16 Vh[BKT][KP];
    __shared__ __align__(32) __nv_bfloat16 Vl[BKT][KP];
    __shared__ __align__(32) __nv_bfloat16 Ph[BQ][PP];
    __shared__ __align__(32) __nv_bfloat16 Pl[BQ][PP];
    __shared__ __align__(32) float SsOs[BQ][OP];   // Q staging, S tile, O tile
    __shared__ float m_s[BQ], l_s[BQ], corr_s[BQ];

    const int tid  = threadIdx.x;
    const int warp = tid >> 5;
    const int wr   = warp >> 1;    // 0..3: 16-row group of q
    const int wc   = warp & 1;     // 0..1: 16-col group (S) / 32-col group (O)
    const int qt   = blockIdx.x;
    const int h    = blockIdx.y;
    const int b    = blockIdx.z;
    const int kv   = h >> 2;

    const size_t qoff = ((size_t)(b * Hc + h) * Tc + qt * BQ) * DHc;
    const size_t koff = (size_t)(b * HKVc + kv) * Tc * DHc;

    // ---- stage Q hi/lo (bf16) into SsOs region, then load fragments ----------
    __nv_bfloat16* Qhs = reinterpret_cast<__nv_bfloat16*>(&SsOs[0][0]);
    __nv_bfloat16* Qls = Qhs + BQ * KP;
#pragma unroll
    for (int j = 0; j < 2; j++) {
        const int i = tid + j * 256;            // 512 uint4 total (64x64 bf16)
        const int r = i >> 3;
        const int c = (i & 7) * 8;
        *reinterpret_cast<uint4*>(Qhs + r * KP + c) =
            *reinterpret_cast<const uint4*>(g_qh + qoff + (size_t)r * DHc + c);
        *reinterpret_cast<uint4*>(Qls + r * KP + c) =
            *reinterpret_cast<const uint4*>(g_ql + qoff + (size_t)r * DHc + c);
    }
    if (tid < BQ) { m_s[tid] = -1e30f; l_s[tid] = 0.f; }
    __syncthreads();

    wmma::fragment<wmma::matrix_a, 16, 16, 16, __nv_bfloat16, wmma::row_major> fQh[4];
    wmma::fragment<wmma::matrix_a, 16, 16, 16, __nv_bfloat16, wmma::row_major> fQl[4];
#pragma unroll
    for (int kd = 0; kd < 4; kd++) {
        wmma::load_matrix_sync(fQh[kd], Qhs + (wr * 16) * KP + kd * 16, KP);
        wmma::load_matrix_sync(fQl[kd], Qls + (wr * 16) * KP + kd * 16, KP);
    }
    __syncthreads();   // Q staging region is reused as S/O below

    float o[4][4];
#pragma unroll
    for (int i = 0; i < 4; i++) {
#pragma unroll
        for (int j = 0; j < 4; j++) { o[i][j] = 0.f; }
    }
    const int qr0  = (tid >> 4) * 4;   // output rows
    const int dc0  = (tid & 15) * 4;   // output cols
    const int srow = tid >> 2;         // softmax row (4 threads per row)
    const int ssub = tid & 3;          // softmax sub-column group (8 cols)
    const int ntiles = 2 * qt + 2;

    // K/V tile loads: 32x64 bf16 = 256 uint4 per array, 1 per thread
    const int lr = tid >> 3;           // 0..31
    const int lc = (tid & 7) * 8;      // 0..56

    uint4 kRegH, kRegL, vRegH, vRegL;
    {
        const size_t off = koff + (size_t)lr * DHc + lc;
        kRegH = *reinterpret_cast<const uint4*>(g_kh + off);
        kRegL = *reinterpret_cast<const uint4*>(g_kl + off);
        vRegH = *reinterpret_cast<const uint4*>(g_vh + off);
        vRegL = *reinterpret_cast<const uint4*>(g_vl + off);
    }

    for (int kt = 0; kt < ntiles; kt++) {
        const int kbase = kt * BKT;

        // ---- store current K/V tile --------------------------------------------
        *reinterpret_cast<uint4*>(&Kh[lr][lc]) = kRegH;
        *reinterpret_cast<uint4*>(&Kl[lr][lc]) = kRegL;
        *reinterpret_cast<uint4*>(&Vh[lr][lc]) = vRegH;
        *reinterpret_cast<uint4*>(&Vl[lr][lc]) = vRegL;
        __syncthreads();   // b1

        // ---- prefetch next tile ------------------------------------------------
        if (kt + 1 < ntiles) {
            const size_t off = koff + (size_t)(kbase + BKT + lr) * DHc + lc;
            kRegH = *reinterpret_cast<const uint4*>(g_kh + off);
            kRegL = *reinterpret_cast<const uint4*>(g_kl + off);
            vRegH = *reinterpret_cast<const uint4*>(g_vh + off);
            vRegL = *reinterpret_cast<const uint4*>(g_vl + off);
        }

        // ---- S = Q K^T (bf16x3), each warp a 16x16 block -----------------------
        {
            wmma::fragment<wmma::accumulator, 16, 16, 16, float> accS;
            wmma::fill_fragment(accS, 0.0f);
#pragma unroll
            for (int kd = 0; kd < 4; kd++) {
                wmma::fragment<wmma::matrix_b, 16, 16, 16, __nv_bfloat16, wmma::col_major> fKh;
                wmma::fragment<wmma::matrix_b, 16, 16, 16, __nv_bfloat16, wmma::col_major> fKl;
                wmma::load_matrix_sync(fKh, &Kh[wc * 16][kd * 16], KP);
                wmma::load_matrix_sync(fKl, &Kl[wc * 16][kd * 16], KP);
                wmma::mma_sync(accS, fQh[kd], fKh, accS);
                wmma::mma_sync(accS, fQh[kd], fKl, accS);
                wmma::mma_sync(accS, fQl[kd], fKh, accS);
            }
            wmma::store_matrix_sync(&SsOs[wr * 16][wc * 16], accS, OP, wmma::mem_row_major);
        }
        __syncthreads();   // b2

        // ---- online softmax: 4 threads per row, 8 cols each --------------------
        {
            const int qi = qt * BQ + srow;
            const float mold = m_s[srow];
            float sv[8];
            float mmax = mold;
#pragma unroll
            for (int j = 0; j < 8; j++) {
                const int ccol = ssub * 8 + j;
                const float s = (kbase + ccol <= qi) ? SsOs[srow][ccol] * 0.125f : -1e30f;
                sv[j] = s;
                mmax = fmaxf(mmax, s);
            }
            mmax = fmaxf(mmax, __shfl_xor_sync(0xffffffffu, mmax, 1));
            mmax = fmaxf(mmax, __shfl_xor_sync(0xffffffffu, mmax, 2));
            float lsum = 0.f;
#pragma unroll
            for (int j = 0; j < 8; j++) {
                const float e = __expf(sv[j] - mmax);
                lsum += e;
                const __nv_bfloat16 eh = __float2bfloat16_rn(e);
                Ph[srow][ssub * 8 + j] = eh;
                Pl[srow][ssub * 8 + j] = __float2bfloat16_rn(e - __bfloat162float(eh));
            }
            lsum += __shfl_xor_sync(0xffffffffu, lsum, 1);
            lsum += __shfl_xor_sync(0xffffffffu, lsum, 2);
            if (ssub == 0) {
                const float cr = __expf(mold - mmax);
                m_s[srow]    = mmax;
                l_s[srow]    = l_s[srow] * cr + lsum;
                corr_s[srow] = cr;
            }
        }
        __syncthreads();   // b3

        // ---- O_tile = P V (bf16x3), each warp 16x32 ----------------------------
        {
            wmma::fragment<wmma::accumulator, 16, 16, 16, float> accO[2];
            wmma::fill_fragment(accO[0], 0.0f);
            wmma::fill_fragment(accO[1], 0.0f);
#pragma unroll
            for (int ks = 0; ks < 2; ks++) {
                wmma::fragment<wmma::matrix_a, 16, 16, 16, __nv_bfloat16, wmma::row_major> fPh;
                wmma::fragment<wmma::matrix_a, 16, 16, 16, __nv_bfloat16, wmma::row_major> fPl;
                wmma::load_matrix_sync(fPh, &Ph[wr * 16][ks * 16], PP);
                wmma::load_matrix_sync(fPl, &Pl[wr * 16][ks * 16], PP);
#pragma unroll
                for (int nj = 0; nj < 2; nj++) {
                    wmma::fragment<wmma::matrix_b, 16, 16, 16, __nv_bfloat16, wmma::row_major> fVh;
                    wmma::fragment<wmma::matrix_b, 16, 16, 16, __nv_bfloat16, wmma::row_major> fVl;
                    wmma::load_matrix_sync(fVh, &Vh[ks * 16][wc * 32 + nj * 16], KP);
                    wmma::load_matrix_sync(fVl, &Vl[ks * 16][wc * 32 + nj * 16], KP);
                    wmma::mma_sync(accO[nj], fPh, fVh, accO[nj]);
                    wmma::mma_sync(accO[nj], fPh, fVl, accO[nj]);
                    wmma::mma_sync(accO[nj], fPl, fVh, accO[nj]);
                }
            }
            wmma::store_matrix_sync(&SsOs[wr * 16][wc * 32],      accO[0], OP, wmma::mem_row_major);
            wmma::store_matrix_sync(&SsOs[wr * 16][wc * 32 + 16], accO[1], OP, wmma::mem_row_major);
        }
        __syncthreads();   // b4

        // ---- rescale + accumulate into register O ------------------------------
#pragma unroll
        for (int i = 0; i < 4; i++) {
            const float cr = corr_s[qr0 + i];
#pragma unroll
            for (int j = 0; j < 4; j++) {
                o[i][j] = o[i][j] * cr + SsOs[qr0 + i][dc0 + j];
            }
        }
        // no end barrier: next iteration writes Kh/Vh (disjoint from SsOs),
        // and next write to SsOs (S store) is after b1+b2.
    }

    // ---- normalize, split hi/lo, write ctx[b][t][h*DH + d] -------------------
#pragma unroll
    for (int i = 0; i < 4; i++) {
        const float inv = 1.f / l_s[qr0 + i];
        const size_t off =
            (size_t)(b * Tc + qt * BQ + qr0 + i) * Dc + h * DHc + dc0;
        float v[4];
#pragma unroll
        for (int j = 0; j < 4; j++) { v[j] = o[i][j] * inv; }
        const __nv_bfloat16 h0 = __float2bfloat16_rn(v[0]);
        const __nv_bfloat16 h1 = __float2bfloat16_rn(v[1]);
        const __nv_bfloat16 h2 = __float2bfloat16_rn(v[2]);
        const __nv_bfloat16 h3 = __float2bfloat16_rn(v[3]);
        __nv_bfloat162* ph = reinterpret_cast<__nv_bfloat162*>(g_ctxh + off);
        ph[0] = __halves2bfloat162(h0, h1);
        ph[1] = __halves2bfloat162(h2, h3);
        __nv_bfloat162* pl = reinterpret_cast<__nv_bfloat162*>(g_ctxl + off);
        pl[0] = __halves2bfloat162(__float2bfloat16_rn(v[0] - __bfloat162float(h0)),
                                   __float2bfloat16_rn(v[1] - __bfloat162float(h1)));
        pl[1] = __halves2bfloat162(__float2bfloat16_rn(v[2] - __bfloat162float(h2)),
                                   __float2bfloat16_rn(v[3] - __bfloat162float(h3)));
    }
}

// ---------------- launch ------------------------------------------------------
extern "C" void kernel_launch(void* const* d_in, const int* in_sizes, int n_in,
                              void* d_out, int out_size) {
    const float* x  = (const float*)d_in[0];
    const float* Wq = (const float*)d_in[1];
    const float* Wk = (const float*)d_in[2];
    const float* Wv = (const float*)d_in[3];
    const float* Wo = (const float*)d_in[4];
    float* out = (float*)d_out;

    // pre-split inputs and weights to bf16 hi/lo
    k_split_x <<<(BT * Dc)  / 1024, 256>>>(x);
    k_split_wq<<<(Dc * Dc)  / 1024, 256>>>(Wq);
    k_split_wk<<<(Dc * DKV) / 1024, 256>>>(Wk);
    k_split_wv<<<(Dc * DKV) / 1024, 256>>>(Wv);
    k_split_wo<<<(Dc * Dc)  / 1024, 256>>>(Wo);

    dim3 gridBig(Dc / 128, BT / 128);
    dim3 gridKV(DKV / 128, BT / 128);

    k_qproj<<<gridBig, 256>>>();

    k_rope_table<<<(Tc * 32) / 256, 256>>>();
    k_kproj<<<gridKV, 256>>>();
    k_vproj<<<gridKV, 256>>>();

    rope_q_kernel<<<(BT * Dc) / 256, 256>>>();
    rope_k_kernel<<<(BT * DKV) / 256, 256>>>();
    k_split_v<<<(BT * DKV) / 1024, 256>>>();

    attn_kernel<<<dim3(Tc / 64, Hc, Bc), 256>>>();

    k_oproj<<<gridBig, 256>>>(out);
}

// round 14
// speedup vs baseline: 1.0306x; 1.0306x over previous
#include <cuda_runtime.h>
#include <cuda_bf16.h>
#include <mma.h>
#include <math.h>

using namespace nvcuda;

// Problem constants
constexpr int Bc   = 2;
constexpr int Tc   = 2048;
constexpr int Dc   = 2048;
constexpr int Hc   = 32;
constexpr int HKVc = 8;
constexpr int DHc  = 64;
constexpr int BT   = Bc * Tc;          // 4096
constexpr int DKV  = HKVc * DHc;       // 512

// ---------------- scratch (__device__ globals, no allocation) ----------------
// NOTE: only ever referenced from DEVICE code (never passed from host).
__device__ float g_qraw[BT * Dc];
__device__ float g_kraw[BT * DKV];
__device__ float g_vraw[BT * DKV];

// pre-split bf16 hi/lo operand buffers
__device__ __nv_bfloat16 g_xh [BT * Dc],  g_xl [BT * Dc];
__device__ __nv_bfloat16 g_wqh[Dc * Dc],  g_wql[Dc * Dc];
__device__ __nv_bfloat16 g_wkh[Dc * DKV], g_wkl[Dc * DKV];
__device__ __nv_bfloat16 g_wvh[Dc * DKV], g_wvl[Dc * DKV];
__device__ __nv_bfloat16 g_woh[Dc * Dc],  g_wol[Dc * Dc];
__device__ __nv_bfloat16 g_qh [BT * Dc],  g_ql [BT * Dc];   // [B,H,T,DH] roped
__device__ __nv_bfloat16 g_kh [BT * DKV], g_kl [BT * DKV];  // [B,HKV,T,DH] roped
__device__ __nv_bfloat16 g_vh [BT * DKV], g_vl [BT * DKV];  // [B,HKV,T,DH]
__device__ __nv_bfloat16 g_ctxh[BT * Dc], g_ctxl[BT * Dc];  // attention out hi/lo

// RoPE tables: [T][32]
__device__ float g_rc[Tc * 32], g_rs[Tc * 32];

// ---------------- helpers -----------------------------------------------------
__device__ __forceinline__ void split4(const float4 v,
                                       __nv_bfloat16* hi, __nv_bfloat16* lo) {
    const __nv_bfloat16 hx = __float2bfloat16_rn(v.x);
    const __nv_bfloat16 hy = __float2bfloat16_rn(v.y);
    const __nv_bfloat16 hz = __float2bfloat16_rn(v.z);
    const __nv_bfloat16 hw = __float2bfloat16_rn(v.w);
    __nv_bfloat162* h2 = reinterpret_cast<__nv_bfloat162*>(hi);
    __nv_bfloat162* l2 = reinterpret_cast<__nv_bfloat162*>(lo);
    h2[0] = __halves2bfloat162(hx, hy);
    h2[1] = __halves2bfloat162(hz, hw);
    l2[0] = __halves2bfloat162(__float2bfloat16_rn(v.x - __bfloat162float(hx)),
                               __float2bfloat16_rn(v.y - __bfloat162float(hy)));
    l2[1] = __halves2bfloat162(__float2bfloat16_rn(v.z - __bfloat162float(hz)),
                               __float2bfloat16_rn(v.w - __bfloat162float(hw)));
}

// ---------------- elementwise split kernels -----------------------------------
__global__ __launch_bounds__(256) void k_split_x(const float* __restrict__ src) {
    const int i = blockIdx.x * 256 + threadIdx.x;
    const float4 v = reinterpret_cast<const float4*>(src)[i];
    split4(v, g_xh + (size_t)i * 4, g_xl + (size_t)i * 4);
}
__global__ __launch_bounds__(256) void k_split_wq(const float* __restrict__ src) {
    const int i = blockIdx.x * 256 + threadIdx.x;
    const float4 v = reinterpret_cast<const float4*>(src)[i];
    split4(v, g_wqh + (size_t)i * 4, g_wql + (size_t)i * 4);
}
__global__ __launch_bounds__(256) void k_split_wk(const float* __restrict__ src) {
    const int i = blockIdx.x * 256 + threadIdx.x;
    const float4 v = reinterpret_cast<const float4*>(src)[i];
    split4(v, g_wkh + (size_t)i * 4, g_wkl + (size_t)i * 4);
}
__global__ __launch_bounds__(256) void k_split_wv(const float* __restrict__ src) {
    const int i = blockIdx.x * 256 + threadIdx.x;
    const float4 v = reinterpret_cast<const float4*>(src)[i];
    split4(v, g_wvh + (size_t)i * 4, g_wvl + (size_t)i * 4);
}
__global__ __launch_bounds__(256) void k_split_wo(const float* __restrict__ src) {
    const int i = blockIdx.x * 256 + threadIdx.x;
    const float4 v = reinterpret_cast<const float4*>(src)[i];
    split4(v, g_woh + (size_t)i * 4, g_wol + (size_t)i * 4);
}
// V: [B,T,HKV*DH] -> [B,HKV,T,DH], split to hi/lo
__global__ __launch_bounds__(256) void k_split_v() {
    const int i4 = blockIdx.x * 256 + threadIdx.x;   // over BT*DKV/4
    const int e  = i4 * 4;
    const int d  = e & 63;
    const int t  = (e >> 6) & 2047;
    const int kv = (e >> 17) & 7;
    const int b  = e >> 20;
    const float4 v = *reinterpret_cast<const float4*>(
        g_vraw + (size_t)(b * Tc + t) * DKV + kv * DHc + d);
    split4(v, g_vh + e, g_vl + e);
}

// ---------------- RoPE table ---------------------------------------------------
#define ROPE_LN_C 0.28782313662425575f

__global__ __launch_bounds__(256) void k_rope_table() {
    const int idx = blockIdx.x * 256 + threadIdx.x;   // over Tc*32
    const int t = idx >> 5;
    const int i = idx & 31;
    const float ang = (float)t * expf(-(float)i * ROPE_LN_C);
    g_rc[idx] = cosf(ang);
    g_rs[idx] = sinf(ang);
}

// ---------------- pure bf16 GEMM via wmma (BK=32, reg prefetch) --------------
// C[4096, N] = (Ah+Al)[4096, 2048] @ (Bh+Bl)[2048, N]  (bf16x3: drops Al*Bl)
// block = 256 (8 warps: 4 along M x 2 along N), CTA tile 128x128, BK=32.
template <int N>
__device__ __forceinline__ void bf16_gemm_body(const __nv_bfloat16* __restrict__ Ahg,
                                               const __nv_bfloat16* __restrict__ Alg,
                                               const __nv_bfloat16* __restrict__ Bhg,
                                               const __nv_bfloat16* __restrict__ Blg,
                                               float* __restrict__ C) {
    constexpr int K  = 2048;
    constexpr int BM = 128, BN = 128, BK = 32;
    constexpr int ASTR = BK + 8;   // 40 bf16 = 80 B per row
    constexpr int BSTR = BN + 8;   // 136 bf16 = 272 B per row

    __shared__ __align__(32) __nv_bfloat16 Ah[BM][ASTR];
    __shared__ __align__(32) __nv_bfloat16 Al[BM][ASTR];
    __shared__ __align__(32) __nv_bfloat16 Bh[BK][BSTR];
    __shared__ __align__(32) __nv_bfloat16 Bl[BK][BSTR];

    const int tid  = threadIdx.x;
    const int warp = tid >> 5;
    const int wm   = (warp >> 1) * 32;
    const int wn   = (warp & 1) * 64;
    const int brow = blockIdx.y * BM;
    const int bcol = blockIdx.x * BN;

    const int ar0 = tid >> 2;              // A row of first vec (0..63)
    const int ac  = (tid & 3) * 8;         // A col (bf16 units)
    const int br0 = tid >> 4;              // B row of first vec (0..15)
    const int bc  = (tid & 15) * 8;

    wmma::fragment<wmma::accumulator, 16, 16, 16, float> acc[2][4];
#pragma unroll
    for (int mi = 0; mi < 2; mi++) {
#pragma unroll
        for (int nj = 0; nj < 4; nj++) {
            wmma::fill_fragment(acc[mi][nj], 0.0f);
        }
    }

    uint4 ahR[2], alR[2], bhR[2], blR[2];
    // load tile 0
#pragma unroll
    for (int j = 0; j < 2; j++) {
        const size_t aoff = (size_t)(brow + ar0 + j * 64) * K + ac;
        ahR[j] = *reinterpret_cast<const uint4*>(Ahg + aoff);
        alR[j] = *reinterpret_cast<const uint4*>(Alg + aoff);
        const size_t boff = (size_t)(br0 + j * 16) * N + bcol + bc;
        bhR[j] = *reinterpret_cast<const uint4*>(Bhg + boff);
        blR[j] = *reinterpret_cast<const uint4*>(Blg + boff);
    }
    // store tile 0
#pragma unroll
    for (int j = 0; j < 2; j++) {
        *reinterpret_cast<uint4*>(&Ah[ar0 + j * 64][ac]) = ahR[j];
        *reinterpret_cast<uint4*>(&Al[ar0 + j * 64][ac]) = alR[j];
        *reinterpret_cast<uint4*>(&Bh[br0 + j * 16][bc]) = bhR[j];
        *reinterpret_cast<uint4*>(&Bl[br0 + j * 16][bc]) = blR[j];
    }

    for (int kt = 0; kt < K / BK; kt++) {
        __syncthreads();

        // issue global loads for next tile
        if (kt + 1 < K / BK) {
            const int k0 = (kt + 1) * BK;
#pragma unroll
            for (int j = 0; j < 2; j++) {
                const size_t aoff = (size_t)(brow + ar0 + j * 64) * K + k0 + ac;
                ahR[j] = *reinterpret_cast<const uint4*>(Ahg + aoff);
                alR[j] = *reinterpret_cast<const uint4*>(Alg + aoff);
                const size_t boff = (size_t)(k0 + br0 + j * 16) * N + bcol + bc;
                bhR[j] = *reinterpret_cast<const uint4*>(Bhg + boff);
                blR[j] = *reinterpret_cast<const uint4*>(Blg + boff);
            }
        }

#pragma unroll
        for (int ks = 0; ks < 2; ks++) {
            wmma::fragment<wmma::matrix_a, 16, 16, 16, __nv_bfloat16, wmma::row_major> fAh[2];
            wmma::fragment<wmma::matrix_a, 16, 16, 16, __nv_bfloat16, wmma::row_major> fAl[2];
#pragma unroll
            for (int mi = 0; mi < 2; mi++) {
                wmma::load_matrix_sync(fAh[mi], &Ah[wm + mi * 16][ks * 16], ASTR);
                wmma::load_matrix_sync(fAl[mi], &Al[wm + mi * 16][ks * 16], ASTR);
            }
#pragma unroll
            for (int nj = 0; nj < 4; nj++) {
                wmma::fragment<wmma::matrix_b, 16, 16, 16, __nv_bfloat16, wmma::row_major> fBh;
                wmma::fragment<wmma::matrix_b, 16, 16, 16, __nv_bfloat16, wmma::row_major> fBl;
                wmma::load_matrix_sync(fBh, &Bh[ks * 16][wn + nj * 16], BSTR);
                wmma::load_matrix_sync(fBl, &Bl[ks * 16][wn + nj * 16], BSTR);
#pragma unroll
                for (int mi = 0; mi < 2; mi++) {
                    wmma::mma_sync(acc[mi][nj], fAh[mi], fBh, acc[mi][nj]);
                    wmma::mma_sync(acc[mi][nj], fAh[mi], fBl, acc[mi][nj]);
                    wmma::mma_sync(acc[mi][nj], fAl[mi], fBh, acc[mi][nj]);
                }
            }
        }

        // store next tile after compute; next loop-top sync protects readers
        if (kt + 1 < K / BK) {
            __syncthreads();
#pragma unroll
            for (int j = 0; j < 2; j++) {
                *reinterpret_cast<uint4*>(&Ah[ar0 + j * 64][ac]) = ahR[j];
                *reinterpret_cast<uint4*>(&Al[ar0 + j * 64][ac]) = alR[j];
                *reinterpret_cast<uint4*>(&Bh[br0 + j * 16][bc]) = bhR[j];
                *reinterpret_cast<uint4*>(&Bl[br0 + j * 16][bc]) = blR[j];
            }
        }
    }

#pragma unroll
    for (int mi = 0; mi < 2; mi++) {
#pragma unroll
        for (int nj = 0; nj < 4; nj++) {
            float* p = C + (size_t)(brow + wm + mi * 16) * N + bcol + wn + nj * 16;
            wmma::store_matrix_sync(p, acc[mi][nj], N, wmma::mem_row_major);
        }
    }
}

// Wrappers: scratch globals referenced from DEVICE code only.
__global__ __launch_bounds__(256) void k_qproj() {
    bf16_gemm_body<Dc>(g_xh, g_xl, g_wqh, g_wql, g_qraw);
}
__global__ __launch_bounds__(256) void k_kproj() {
    bf16_gemm_body<DKV>(g_xh, g_xl, g_wkh, g_wkl, g_kraw);
}
__global__ __launch_bounds__(256) void k_vproj() {
    bf16_gemm_body<DKV>(g_xh, g_xl, g_wvh, g_wvl, g_vraw);
}
__global__ __launch_bounds__(256) void k_oproj(float* __restrict__ out) {
    bf16_gemm_body<Dc>(g_ctxh, g_ctxl, g_woh, g_wol, out);
}

// ---------------- RoPE (table lookup, fused hi/lo split output) ---------------
__global__ __launch_bounds__(256) void rope_q_kernel() {
    const int idx = blockIdx.x * 256 + threadIdx.x;   // over [B,H,T,DH]
    const int d = idx & 63;
    const int t = (idx >> 6) & 2047;
    const int h = (idx >> 17) & 31;
    const int b = idx >> 22;
    const size_t row = (size_t)(b * Tc + t) * Dc + h * DHc;
    const float raw  = g_qraw[row + d];
    const float pair = g_qraw[row + ((d < 32) ? d + 32 : d - 32)];
    const float rot  = (d < 32) ? -pair : pair;
    const int   ti   = t * 32 + (d & 31);
    const float val  = raw * g_rc[ti] + rot * g_rs[ti];
    const __nv_bfloat16 hi = __float2bfloat16_rn(val);
    g_qh[idx] = hi;
    g_ql[idx] = __float2bfloat16_rn(val - __bfloat162float(hi));
}

__global__ __launch_bounds__(256) void rope_k_kernel() {
    const int idx = blockIdx.x * 256 + threadIdx.x;   // over [B,HKV,T,DH]
    const int d  = idx & 63;
    const int t  = (idx >> 6) & 2047;
    const int kv = (idx >> 17) & 7;
    const int b  = idx >> 20;
    const size_t row = (size_t)(b * Tc + t) * DKV + kv * DHc;
    const float raw  = g_kraw[row + d];
    const float pair = g_kraw[row + ((d < 32) ? d + 32 : d - 32)];
    const float rot  = (d < 32) ? -pair : pair;
    const int   ti   = t * 32 + (d & 31);
    const float val  = raw * g_rc[ti] + rot * g_rs[ti];
    const __nv_bfloat16 hi = __float2bfloat16_rn(val);
    g_kh[idx] = hi;
    g_kl[idx] = __float2bfloat16_rn(val - __bfloat162float(hi));
}

// ---------------- Causal flash attention (bf16x3 wmma, parallel softmax) -----
// grid: (H*B, T/64) with LPT order: qt = T/64-1 - blockIdx.y (longest first).
// block: 256 (8 warps: 4 along q x 2 along key/dh)
__global__ __launch_bounds__(256) void attn_kernel() {
    constexpr int BQ  = 64;
    constexpr int BKT = 32;
    constexpr int KP  = 72;   // bf16 row stride for K/V/Q-staging
    constexpr int PP  = 40;   // bf16 row stride for P
    constexpr int OP  = 72;   // fp32 row stride for Ss/Os

    __shared__ __align__(32) __nv_bfloat16 Kh[BKT][KP];
    __shared__ __align__(32) __nv_bfloat16 Kl[BKT][KP];
    __shared__ __align__(32) __nv_bfloat16 Vh[BKT][KP];
    __shared__ __align__(32) __nv_bfloat16 Vl[BKT][KP];
    __shared__ __align__(32) __nv_bfloat16 Ph[BQ][PP];
    __shared__ __align__(32) __nv_bfloat16 Pl[BQ][PP];
    __shared__ __align__(32) float SsOs[BQ][OP];   // Q staging, S tile, O tile
    __shared__ float m_s[BQ], l_s[BQ], corr_s[BQ];

    const int tid  = threadIdx.x;
    const int warp = tid >> 5;
    const int wr   = warp >> 1;    // 0..3: 16-row group of q
    const int wc   = warp & 1;     // 0..1: 16-col group (S) / 32-col group (O)
    const int h    = blockIdx.x & 31;
    const int b    = blockIdx.x >> 5;
    const int qt   = (Tc / 64 - 1) - blockIdx.y;   // LPT: longest jobs first
    const int kv   = h >> 2;

    const size_t qoff = ((size_t)(b * Hc + h) * Tc + qt * BQ) * DHc;
    const size_t koff = (size_t)(b * HKVc + kv) * Tc * DHc;

    // ---- stage Q hi/lo (bf16) into SsOs region, then load fragments ----------
    __nv_bfloat16* Qhs = reinterpret_cast<__nv_bfloat16*>(&SsOs[0][0]);
    __nv_bfloat16* Qls = Qhs + BQ * KP;
#pragma unroll
    for (int j = 0; j < 2; j++) {
        const int i = tid + j * 256;            // 512 uint4 total (64x64 bf16)
        const int r = i >> 3;
        const int c = (i & 7) * 8;
        *reinterpret_cast<uint4*>(Qhs + r * KP + c) =
            *reinterpret_cast<const uint4*>(g_qh + qoff + (size_t)r * DHc + c);
        *reinterpret_cast<uint4*>(Qls + r * KP + c) =
            *reinterpret_cast<const uint4*>(g_ql + qoff + (size_t)r * DHc + c);
    }
    if (tid < BQ) { m_s[tid] = -1e30f; l_s[tid] = 0.f; }
    __syncthreads();

    wmma::fragment<wmma::matrix_a, 16, 16, 16, __nv_bfloat16, wmma::row_major> fQh[4];
    wmma::fragment<wmma::matrix_a, 16, 16, 16, __nv_bfloat16, wmma::row_major> fQl[4];
#pragma unroll
    for (int kd = 0; kd < 4; kd++) {
        wmma::load_matrix_sync(fQh[kd], Qhs + (wr * 16) * KP + kd * 16, KP);
        wmma::load_matrix_sync(fQl[kd], Qls + (wr * 16) * KP + kd * 16, KP);
    }
    __syncthreads();   // Q staging region is reused as S/O below

    float o[4][4];
#pragma unroll
    for (int i = 0; i < 4; i++) {
#pragma unroll
        for (int j = 0; j < 4; j++) { o[i][j] = 0.f; }
    }
    const int qr0  = (tid >> 4) * 4;   // output rows
    const int dc0  = (tid & 15) * 4;   // output cols
    const int srow = tid >> 2;         // softmax row (4 threads per row)
    const int ssub = tid & 3;          // softmax sub-column group (8 cols)
    const int ntiles = 2 * qt + 2;

    // K/V tile loads: 32x64 bf16 = 256 uint4 per array, 1 per thread
    const int lr = tid >> 3;           // 0..31
    const int lc = (tid & 7) * 8;      // 0..56

    uint4 kRegH, kRegL, vRegH, vRegL;
    {
        const size_t off = koff + (size_t)lr * DHc + lc;
        kRegH = *reinterpret_cast<const uint4*>(g_kh + off);
        kRegL = *reinterpret_cast<const uint4*>(g_kl + off);
        vRegH = *reinterpret_cast<const uint4*>(g_vh + off);
        vRegL = *reinterpret_cast<const uint4*>(g_vl + off);
    }

    for (int kt = 0; kt < ntiles; kt++) {
        const int kbase = kt * BKT;

        // ---- store current K/V tile --------------------------------------------
        *reinterpret_cast<uint4*>(&Kh[lr][lc]) = kRegH;
        *reinterpret_cast<uint4*>(&Kl[lr][lc]) = kRegL;
        *reinterpret_cast<uint4*>(&Vh[lr][lc]) = vRegH;
        *reinterpret_cast<uint4*>(&Vl[lr][lc]) = vRegL;
        __syncthreads();   // b1

        // ---- prefetch next tile ------------------------------------------------
        if (kt + 1 < ntiles) {
            const size_t off = koff + (size_t)(kbase + BKT + lr) * DHc + lc;
            kRegH = *reinterpret_cast<const uint4*>(g_kh + off);
            kRegL = *reinterpret_cast<const uint4*>(g_kl + off);
            vRegH = *reinterpret_cast<const uint4*>(g_vh + off);
            vRegL = *reinterpret_cast<const uint4*>(g_vl + off);
        }

        // ---- S = Q K^T (bf16x3), each warp a 16x16 block -----------------------
        {
            wmma::fragment<wmma::accumulator, 16, 16, 16, float> accS;
            wmma::fill_fragment(accS, 0.0f);
#pragma unroll
            for (int kd = 0; kd < 4; kd++) {
                wmma::fragment<wmma::matrix_b, 16, 16, 16, __nv_bfloat16, wmma::col_major> fKh;
                wmma::fragment<wmma::matrix_b, 16, 16, 16, __nv_bfloat16, wmma::col_major> fKl;
                wmma::load_matrix_sync(fKh, &Kh[wc * 16][kd * 16], KP);
                wmma::load_matrix_sync(fKl, &Kl[wc * 16][kd * 16], KP);
                wmma::mma_sync(accS, fQh[kd], fKh, accS);
                wmma::mma_sync(accS, fQh[kd], fKl, accS);
                wmma::mma_sync(accS, fQl[kd], fKh, accS);
            }
            wmma::store_matrix_sync(&SsOs[wr * 16][wc * 16], accS, OP, wmma::mem_row_major);
        }
        __syncthreads();   // b2

        // ---- online softmax: 4 threads per row, 8 cols each --------------------
        {
            const int qi = qt * BQ + srow;
            const float mold = m_s[srow];
            float sv[8];
            float mmax = mold;
#pragma unroll
            for (int j = 0; j < 8; j++) {
                const int ccol = ssub * 8 + j;
                const float s = (kbase + ccol <= qi) ? SsOs[srow][ccol] * 0.125f : -1e30f;
                sv[j] = s;
                mmax = fmaxf(mmax, s);
            }
            mmax = fmaxf(mmax, __shfl_xor_sync(0xffffffffu, mmax, 1));
            mmax = fmaxf(mmax, __shfl_xor_sync(0xffffffffu, mmax, 2));
            float lsum = 0.f;
#pragma unroll
            for (int j = 0; j < 8; j++) {
                const float e = __expf(sv[j] - mmax);
                lsum += e;
                const __nv_bfloat16 eh = __float2bfloat16_rn(e);
                Ph[srow][ssub * 8 + j] = eh;
                Pl[srow][ssub * 8 + j] = __float2bfloat16_rn(e - __bfloat162float(eh));
            }
            lsum += __shfl_xor_sync(0xffffffffu, lsum, 1);
            lsum += __shfl_xor_sync(0xffffffffu, lsum, 2);
            if (ssub == 0) {
                const float cr = __expf(mold - mmax);
                m_s[srow]    = mmax;
                l_s[srow]    = l_s[srow] * cr + lsum;
                corr_s[srow] = cr;
            }
        }
        __syncthreads();   // b3

        // ---- O_tile = P V (bf16x3), each warp 16x32 ----------------------------
        {
            wmma::fragment<wmma::accumulator, 16, 16, 16, float> accO[2];
            wmma::fill_fragment(accO[0], 0.0f);
            wmma::fill_fragment(accO[1], 0.0f);
#pragma unroll
            for (int ks = 0; ks < 2; ks++) {
                wmma::fragment<wmma::matrix_a, 16, 16, 16, __nv_bfloat16, wmma::row_major> fPh;
                wmma::fragment<wmma::matrix_a, 16, 16, 16, __nv_bfloat16, wmma::row_major> fPl;
                wmma::load_matrix_sync(fPh, &Ph[wr * 16][ks * 16], PP);
                wmma::load_matrix_sync(fPl, &Pl[wr * 16][ks * 16], PP);
#pragma unroll
                for (int nj = 0; nj < 2; nj++) {
                    wmma::fragment<wmma::matrix_b, 16, 16, 16, __nv_bfloat16, wmma::row_major> fVh;
                    wmma::fragment<wmma::matrix_b, 16, 16, 16, __nv_bfloat16, wmma::row_major> fVl;
                    wmma::load_matrix_sync(fVh, &Vh[ks * 16][wc * 32 + nj * 16], KP);
                    wmma::load_matrix_sync(fVl, &Vl[ks * 16][wc * 32 + nj * 16], KP);
                    wmma::mma_sync(accO[nj], fPh, fVh, accO[nj]);
                    wmma::mma_sync(accO[nj], fPh, fVl, accO[nj]);
                    wmma::mma_sync(accO[nj], fPl, fVh, accO[nj]);
                }
            }
            wmma::store_matrix_sync(&SsOs[wr * 16][wc * 32],      accO[0], OP, wmma::mem_row_major);
            wmma::store_matrix_sync(&SsOs[wr * 16][wc * 32 + 16], accO[1], OP, wmma::mem_row_major);
        }
        __syncthreads();   // b4

        // ---- rescale + accumulate into register O ------------------------------
#pragma unroll
        for (int i = 0; i < 4; i++) {
            const float cr = corr_s[qr0 + i];
#pragma unroll
            for (int j = 0; j < 4; j++) {
                o[i][j] = o[i][j] * cr + SsOs[qr0 + i][dc0 + j];
            }
        }
        // no end barrier: next iteration writes Kh/Vh (disjoint from SsOs),
        // and next write to SsOs (S store) is after b1+b2.
    }

    // ---- normalize, split hi/lo, write ctx[b][t][h*DH + d] -------------------
#pragma unroll
    for (int i = 0; i < 4; i++) {
        const float inv = 1.f / l_s[qr0 + i];
        const size_t off =
            (size_t)(b * Tc + qt * BQ + qr0 + i) * Dc + h * DHc + dc0;
        float v[4];
#pragma unroll
        for (int j = 0; j < 4; j++) { v[j] = o[i][j] * inv; }
        const __nv_bfloat16 h0 = __float2bfloat16_rn(v[0]);
        const __nv_bfloat16 h1 = __float2bfloat16_rn(v[1]);
        const __nv_bfloat16 h2 = __float2bfloat16_rn(v[2]);
        const __nv_bfloat16 h3 = __float2bfloat16_rn(v[3]);
        __nv_bfloat162* ph = reinterpret_cast<__nv_bfloat162*>(g_ctxh + off);
        ph[0] = __halves2bfloat162(h0, h1);
        ph[1] = __halves2bfloat162(h2, h3);
        __nv_bfloat162* pl = reinterpret_cast<__nv_bfloat162*>(g_ctxl + off);
        pl[0] = __halves2bfloat162(__float2bfloat16_rn(v[0] - __bfloat162float(h0)),
                                   __float2bfloat16_rn(v[1] - __bfloat162float(h1)));
        pl[1] = __halves2bfloat162(__float2bfloat16_rn(v[2] - __bfloat162float(h2)),
                                   __float2bfloat16_rn(v[3] - __bfloat162float(h3)));
    }
}

// ---------------- launch ------------------------------------------------------
extern "C" void kernel_launch(void* const* d_in, const int* in_sizes, int n_in,
                              void* d_out, int out_size) {
    const float* x  = (const float*)d_in[0];
    const float* Wq = (const float*)d_in[1];
    const float* Wk = (const float*)d_in[2];
    const float* Wv = (const float*)d_in[3];
    const float* Wo = (const float*)d_in[4];
    float* out = (float*)d_out;

    // pre-split inputs and weights to bf16 hi/lo
    k_split_x <<<(BT * Dc)  / 1024, 256>>>(x);
    k_split_wq<<<(Dc * Dc)  / 1024, 256>>>(Wq);
    k_split_wk<<<(Dc * DKV) / 1024, 256>>>(Wk);
    k_split_wv<<<(Dc * DKV) / 1024, 256>>>(Wv);
    k_split_wo<<<(Dc * Dc)  / 1024, 256>>>(Wo);

    dim3 gridBig(Dc / 128, BT / 128);
    dim3 gridKV(DKV / 128, BT / 128);

    k_qproj<<<gridBig, 256>>>();

    k_rope_table<<<(Tc * 32) / 256, 256>>>();
    k_kproj<<<gridKV, 256>>>();
    k_vproj<<<gridKV, 256>>>();

    rope_q_kernel<<<(BT * Dc) / 256, 256>>>();
    rope_k_kernel<<<(BT * DKV) / 256, 256>>>();
    k_split_v<<<(BT * DKV) / 1024, 256>>>();

    attn_kernel<<<dim3(Hc * Bc, Tc / 64), 256>>>();

    k_oproj<<<gridBig, 256>>>(out);
}

// round 15
// speedup vs baseline: 1.1254x; 1.0919x over previous
#include <cuda_runtime.h>
#include <cuda_bf16.h>
#include <mma.h>
#include <math.h>

using namespace nvcuda;

// Problem constants
constexpr int Bc   = 2;
constexpr int Tc   = 2048;
constexpr int Dc   = 2048;
constexpr int Hc   = 32;
constexpr int HKVc = 8;
constexpr int DHc  = 64;
constexpr int BT   = Bc * Tc;          // 4096
constexpr int DKV  = HKVc * DHc;       // 512

// ---------------- scratch (__device__ globals, no allocation) ----------------
// NOTE: only ever referenced from DEVICE code (never passed from host).
__device__ float g_qraw[BT * Dc];
__device__ float g_kraw[BT * DKV];
__device__ float g_vraw[BT * DKV];
__device__ float g_ctx [BT * Dc];

// pre-split bf16 hi/lo operand buffers
__device__ __nv_bfloat16 g_xh [BT * Dc],  g_xl [BT * Dc];
__device__ __nv_bfloat16 g_wqh[Dc * Dc],  g_wql[Dc * Dc];
__device__ __nv_bfloat16 g_wkh[Dc * DKV], g_wkl[Dc * DKV];
__device__ __nv_bfloat16 g_wvh[Dc * DKV], g_wvl[Dc * DKV];
__device__ __nv_bfloat16 g_woh[Dc * Dc],  g_wol[Dc * Dc];
__device__ __nv_bfloat16 g_qh [BT * Dc],  g_ql [BT * Dc];   // [B,H,T,DH] roped
__device__ __nv_bfloat16 g_kh [BT * DKV], g_kl [BT * DKV];  // [B,HKV,T,DH] roped
__device__ __nv_bfloat16 g_vh [BT * DKV], g_vl [BT * DKV];  // [B,HKV,T,DH]
__device__ __nv_bfloat16 g_ctxh[BT * Dc], g_ctxl[BT * Dc];

// ---------------- helpers -----------------------------------------------------
__device__ __forceinline__ void split4(const float4 v,
                                       __nv_bfloat16* hi, __nv_bfloat16* lo) {
    const __nv_bfloat16 hx = __float2bfloat16_rn(v.x);
    const __nv_bfloat16 hy = __float2bfloat16_rn(v.y);
    const __nv_bfloat16 hz = __float2bfloat16_rn(v.z);
    const __nv_bfloat16 hw = __float2bfloat16_rn(v.w);
    __nv_bfloat162* h2 = reinterpret_cast<__nv_bfloat162*>(hi);
    __nv_bfloat162* l2 = reinterpret_cast<__nv_bfloat162*>(lo);
    h2[0] = __halves2bfloat162(hx, hy);
    h2[1] = __halves2bfloat162(hz, hw);
    l2[0] = __halves2bfloat162(__float2bfloat16_rn(v.x - __bfloat162float(hx)),
                               __float2bfloat16_rn(v.y - __bfloat162float(hy)));
    l2[1] = __halves2bfloat162(__float2bfloat16_rn(v.z - __bfloat162float(hz)),
                               __float2bfloat16_rn(v.w - __bfloat162float(hw)));
}

// ---------------- elementwise split kernels -----------------------------------
__global__ __launch_bounds__(256) void k_split_x(const float* __restrict__ src) {
    const int i = blockIdx.x * 256 + threadIdx.x;
    const float4 v = reinterpret_cast<const float4*>(src)[i];
    split4(v, g_xh + (size_t)i * 4, g_xl + (size_t)i * 4);
}
__global__ __launch_bounds__(256) void k_split_wq(const float* __restrict__ src) {
    const int i = blockIdx.x * 256 + threadIdx.x;
    const float4 v = reinterpret_cast<const float4*>(src)[i];
    split4(v, g_wqh + (size_t)i * 4, g_wql + (size_t)i * 4);
}
__global__ __launch_bounds__(256) void k_split_wk(const float* __restrict__ src) {
    const int i = blockIdx.x * 256 + threadIdx.x;
    const float4 v = reinterpret_cast<const float4*>(src)[i];
    split4(v, g_wkh + (size_t)i * 4, g_wkl + (size_t)i * 4);
}
__global__ __launch_bounds__(256) void k_split_wv(const float* __restrict__ src) {
    const int i = blockIdx.x * 256 + threadIdx.x;
    const float4 v = reinterpret_cast<const float4*>(src)[i];
    split4(v, g_wvh + (size_t)i * 4, g_wvl + (size_t)i * 4);
}
__global__ __launch_bounds__(256) void k_split_wo(const float* __restrict__ src) {
    const int i = blockIdx.x * 256 + threadIdx.x;
    const float4 v = reinterpret_cast<const float4*>(src)[i];
    split4(v, g_woh + (size_t)i * 4, g_wol + (size_t)i * 4);
}
__global__ __launch_bounds__(256) void k_split_ctx() {
    const int i = blockIdx.x * 256 + threadIdx.x;
    const float4 v = reinterpret_cast<const float4*>(g_ctx)[i];
    split4(v, g_ctxh + (size_t)i * 4, g_ctxl + (size_t)i * 4);
}
// V: [B,T,HKV*DH] -> [B,HKV,T,DH], split to hi/lo
__global__ __launch_bounds__(256) void k_split_v() {
    const int i4 = blockIdx.x * 256 + threadIdx.x;   // over BT*DKV/4
    const int e  = i4 * 4;
    const int d  = e & 63;
    const int t  = (e >> 6) & 2047;
    const int kv = (e >> 17) & 7;
    const int b  = e >> 20;
    const float4 v = *reinterpret_cast<const float4*>(
        g_vraw + (size_t)(b * Tc + t) * DKV + kv * DHc + d);
    split4(v, g_vh + e, g_vl + e);
}

// ---------------- pure bf16 GEMM via wmma (device body) ----------------------
// C[4096, N] = (Ah+Al)[4096, 2048] @ (Bh+Bl)[2048, N]  (bf16x3: drops Al*Bl)
// block = 256 (8 warps: 4 along M x 2 along N), CTA tile 128x128, BK=32.
template <int N>
__device__ __forceinline__ void bf16_gemm_body(const __nv_bfloat16* __restrict__ Ahg,
                                               const __nv_bfloat16* __restrict__ Alg,
                                               const __nv_bfloat16* __restrict__ Bhg,
                                               const __nv_bfloat16* __restrict__ Blg,
                                               float* __restrict__ C) {
    constexpr int K  = 2048;
    constexpr int BM = 128, BN = 128, BK = 32;
    constexpr int ASTR = BK + 8;   // 40 bf16 = 80 B per row
    constexpr int BSTR = BN + 8;   // 136 bf16 = 272 B per row

    __shared__ __align__(32) __nv_bfloat16 Ah[BM][ASTR];
    __shared__ __align__(32) __nv_bfloat16 Al[BM][ASTR];
    __shared__ __align__(32) __nv_bfloat16 Bh[BK][BSTR];
    __shared__ __align__(32) __nv_bfloat16 Bl[BK][BSTR];

    const int tid  = threadIdx.x;
    const int warp = tid >> 5;
    const int wm   = (warp >> 1) * 32;
    const int wn   = (warp & 1) * 64;
    const int brow = blockIdx.y * BM;
    const int bcol = blockIdx.x * BN;

    // A tile: 128x32 bf16 = 512 uint4 per array; 2 per thread
    const int ar0 = tid >> 2;              // row of first A vec (0..63)
    const int ac  = (tid & 3) * 8;         // col (bf16 units)
    // B tile: 32x128 bf16 = 512 uint4 per array; 2 per thread
    const int br0 = tid >> 4;              // row of first B vec (0..15)
    const int bc  = (tid & 15) * 8;

    wmma::fragment<wmma::accumulator, 16, 16, 16, float> acc[2][4];
#pragma unroll
    for (int mi = 0; mi < 2; mi++) {
#pragma unroll
        for (int nj = 0; nj < 4; nj++) {
            wmma::fill_fragment(acc[mi][nj], 0.0f);
        }
    }

    uint4 ahR[2], alR[2], bhR[2], blR[2];
#pragma unroll
    for (int j = 0; j < 2; j++) {
        const size_t aoff = (size_t)(brow + ar0 + j * 64) * K + ac;
        ahR[j] = *reinterpret_cast<const uint4*>(Ahg + aoff);
        alR[j] = *reinterpret_cast<const uint4*>(Alg + aoff);
        const size_t boff = (size_t)(br0 + j * 16) * N + bcol + bc;
        bhR[j] = *reinterpret_cast<const uint4*>(Bhg + boff);
        blR[j] = *reinterpret_cast<const uint4*>(Blg + boff);
    }

    for (int kt = 0; kt < K / BK; kt++) {
#pragma unroll
        for (int j = 0; j < 2; j++) {
            *reinterpret_cast<uint4*>(&Ah[ar0 + j * 64][ac]) = ahR[j];
            *reinterpret_cast<uint4*>(&Al[ar0 + j * 64][ac]) = alR[j];
            *reinterpret_cast<uint4*>(&Bh[br0 + j * 16][bc]) = bhR[j];
            *reinterpret_cast<uint4*>(&Bl[br0 + j * 16][bc]) = blR[j];
        }
        __syncthreads();

        if (kt + 1 < K / BK) {
            const int k0 = (kt + 1) * BK;
#pragma unroll
            for (int j = 0; j < 2; j++) {
                const size_t aoff = (size_t)(brow + ar0 + j * 64) * K + k0 + ac;
                ahR[j] = *reinterpret_cast<const uint4*>(Ahg + aoff);
                alR[j] = *reinterpret_cast<const uint4*>(Alg + aoff);
                const size_t boff = (size_t)(k0 + br0 + j * 16) * N + bcol + bc;
                bhR[j] = *reinterpret_cast<const uint4*>(Bhg + boff);
                blR[j] = *reinterpret_cast<const uint4*>(Blg + boff);
            }
        }

#pragma unroll
        for (int ks = 0; ks < 2; ks++) {
            wmma::fragment<wmma::matrix_a, 16, 16, 16, __nv_bfloat16, wmma::row_major> fAh[2];
            wmma::fragment<wmma::matrix_a, 16, 16, 16, __nv_bfloat16, wmma::row_major> fAl[2];
#pragma unroll
            for (int mi = 0; mi < 2; mi++) {
                wmma::load_matrix_sync(fAh[mi], &Ah[wm + mi * 16][ks * 16], ASTR);
                wmma::load_matrix_sync(fAl[mi], &Al[wm + mi * 16][ks * 16], ASTR);
            }
#pragma unroll
            for (int nj = 0; nj < 4; nj++) {
                wmma::fragment<wmma::matrix_b, 16, 16, 16, __nv_bfloat16, wmma::row_major> fBh;
                wmma::fragment<wmma::matrix_b, 16, 16, 16, __nv_bfloat16, wmma::row_major> fBl;
                wmma::load_matrix_sync(fBh, &Bh[ks * 16][wn + nj * 16], BSTR);
                wmma::load_matrix_sync(fBl, &Bl[ks * 16][wn + nj * 16], BSTR);
#pragma unroll
                for (int mi = 0; mi < 2; mi++) {
                    wmma::mma_sync(acc[mi][nj], fAh[mi], fBh, acc[mi][nj]);
                    wmma::mma_sync(acc[mi][nj], fAh[mi], fBl, acc[mi][nj]);
                    wmma::mma_sync(acc[mi][nj], fAl[mi], fBh, acc[mi][nj]);
                }
            }
        }
        __syncthreads();
    }

#pragma unroll
    for (int mi = 0; mi < 2; mi++) {
#pragma unroll
        for (int nj = 0; nj < 4; nj++) {
            float* p = C + (size_t)(brow + wm + mi * 16) * N + bcol + wn + nj * 16;
            wmma::store_matrix_sync(p, acc[mi][nj], N, wmma::mem_row_major);
        }
    }
}

// Wrappers: scratch globals referenced from DEVICE code only.
__global__ __launch_bounds__(256) void k_qproj() {
    bf16_gemm_body<Dc>(g_xh, g_xl, g_wqh, g_wql, g_qraw);
}
__global__ __launch_bounds__(256) void k_kproj() {
    bf16_gemm_body<DKV>(g_xh, g_xl, g_wkh, g_wkl, g_kraw);
}
__global__ __launch_bounds__(256) void k_vproj() {
    bf16_gemm_body<DKV>(g_xh, g_xl, g_wvh, g_wvl, g_vraw);
}
__global__ __launch_bounds__(256) void k_oproj(float* __restrict__ out) {
    bf16_gemm_body<Dc>(g_ctxh, g_ctxl, g_woh, g_wol, out);
}

// ---------------- RoPE (fused hi/lo split output) -----------------------------
#define ROPE_LN_C 0.28782313662425575f

__global__ __launch_bounds__(256) void rope_q_kernel() {
    const int idx = blockIdx.x * 256 + threadIdx.x;   // over [B,H,T,DH]
    const int d = idx & 63;
    const int t = (idx >> 6) & 2047;
    const int h = (idx >> 17) & 31;
    const int b = idx >> 22;
    const size_t row = (size_t)(b * Tc + t) * Dc + h * DHc;
    const float raw  = g_qraw[row + d];
    const float pair = g_qraw[row + ((d < 32) ? d + 32 : d - 32)];
    const float rot  = (d < 32) ? -pair : pair;
    const int   i    = d & 31;
    const float invf = expf(-(float)i * ROPE_LN_C);
    const float ang  = (float)t * invf;
    const float val  = raw * cosf(ang) + rot * sinf(ang);
    const __nv_bfloat16 hi = __float2bfloat16_rn(val);
    g_qh[idx] = hi;
    g_ql[idx] = __float2bfloat16_rn(val - __bfloat162float(hi));
}

__global__ __launch_bounds__(256) void rope_k_kernel() {
    const int idx = blockIdx.x * 256 + threadIdx.x;   // over [B,HKV,T,DH]
    const int d  = idx & 63;
    const int t  = (idx >> 6) & 2047;
    const int kv = (idx >> 17) & 7;
    const int b  = idx >> 20;
    const size_t row = (size_t)(b * Tc + t) * DKV + kv * DHc;
    const float raw  = g_kraw[row + d];
    const float pair = g_kraw[row + ((d < 32) ? d + 32 : d - 32)];
    const float rot  = (d < 32) ? -pair : pair;
    const int   i    = d & 31;
    const float invf = expf(-(float)i * ROPE_LN_C);
    const float ang  = (float)t * invf;
    const float val  = raw * cosf(ang) + rot * sinf(ang);
    const __nv_bfloat16 hi = __float2bfloat16_rn(val);
    g_kh[idx] = hi;
    g_kl[idx] = __float2bfloat16_rn(val - __bfloat162float(hi));
}

// ---------------- Causal flash attention (bf16x3 wmma, parallel softmax) -----
// grid: (H*B, T/64) with LPT order: qt = T/64-1 - blockIdx.y (longest first).
// block: 256 (8 warps: 4 along q x 2 along key/dh)
__global__ __launch_bounds__(256) void attn_kernel() {
    constexpr int BQ  = 64;
    constexpr int BKT = 32;
    constexpr int KP  = 72;   // bf16 row stride for K/V/Q-staging
    constexpr int PP  = 40;   // bf16 row stride for P
    constexpr int OP  = 72;   // fp32 row stride for Ss/Os

    __shared__ __align__(32) __nv_bfloat16 Kh[BKT][KP];
    __shared__ __align__(32) __nv_bfloat16 Kl[BKT][KP];
    __shared__ __align__(32) __nv_bfloat16 Vh[BKT][KP];
    __shared__ __align__(32) __nv_bfloat16 Vl[BKT][KP];
    __shared__ __align__(32) __nv_bfloat16 Ph[BQ][PP];
    __shared__ __align__(32) __nv_bfloat16 Pl[BQ][PP];
    __shared__ __align__(32) float SsOs[BQ][OP];   // Q staging, S tile, O tile
    __shared__ float m_s[BQ], l_s[BQ], corr_s[BQ];

    const int tid  = threadIdx.x;
    const int warp = tid >> 5;
    const int wr   = warp >> 1;    // 0..3: 16-row group of q
    const int wc   = warp & 1;     // 0..1: 16-col group (S) / 32-col group (O)
    const int h    = blockIdx.x & 31;
    const int b    = blockIdx.x >> 5;
    const int qt   = (Tc / 64 - 1) - blockIdx.y;   // LPT: longest jobs first
    const int kv   = h >> 2;

    const size_t qoff = ((size_t)(b * Hc + h) * Tc + qt * BQ) * DHc;
    const size_t koff = (size_t)(b * HKVc + kv) * Tc * DHc;

    // ---- stage Q hi/lo (bf16) into SsOs region, then load fragments ----------
    __nv_bfloat16* Qhs = reinterpret_cast<__nv_bfloat16*>(&SsOs[0][0]);
    __nv_bfloat16* Qls = Qhs + BQ * KP;
#pragma unroll
    for (int j = 0; j < 2; j++) {
        const int i = tid + j * 256;            // 512 uint4 total (64x64 bf16)
        const int r = i >> 3;
        const int c = (i & 7) * 8;
        *reinterpret_cast<uint4*>(Qhs + r * KP + c) =
            *reinterpret_cast<const uint4*>(g_qh + qoff + (size_t)r * DHc + c);
        *reinterpret_cast<uint4*>(Qls + r * KP + c) =
            *reinterpret_cast<const uint4*>(g_ql + qoff + (size_t)r * DHc + c);
    }
    if (tid < BQ) { m_s[tid] = -1e30f; l_s[tid] = 0.f; }
    __syncthreads();

    wmma::fragment<wmma::matrix_a, 16, 16, 16, __nv_bfloat16, wmma::row_major> fQh[4];
    wmma::fragment<wmma::matrix_a, 16, 16, 16, __nv_bfloat16, wmma::row_major> fQl[4];
#pragma unroll
    for (int kd = 0; kd < 4; kd++) {
        wmma::load_matrix_sync(fQh[kd], Qhs + (wr * 16) * KP + kd * 16, KP);
        wmma::load_matrix_sync(fQl[kd], Qls + (wr * 16) * KP + kd * 16, KP);
    }
    __syncthreads();   // Q staging region is reused as S/O below

    float o[4][4];
#pragma unroll
    for (int i = 0; i < 4; i++) {
#pragma unroll
        for (int j = 0; j < 4; j++) { o[i][j] = 0.f; }
    }
    const int qr0  = (tid >> 4) * 4;   // output rows
    const int dc0  = (tid & 15) * 4;   // output cols
    const int srow = tid >> 2;         // softmax row (4 threads per row)
    const int ssub = tid & 3;          // softmax sub-column group (8 cols)
    const int ntiles = 2 * qt + 2;

    // K/V tile loads: 32x64 bf16 = 256 uint4 per array, 1 per thread
    const int lr = tid >> 3;           // 0..31
    const int lc = (tid & 7) * 8;      // 0..56

    uint4 kRegH, kRegL, vRegH, vRegL;
    {
        const size_t off = koff + (size_t)lr * DHc + lc;
        kRegH = *reinterpret_cast<const uint4*>(g_kh + off);
        kRegL = *reinterpret_cast<const uint4*>(g_kl + off);
        vRegH = *reinterpret_cast<const uint4*>(g_vh + off);
        vRegL = *reinterpret_cast<const uint4*>(g_vl + off);
    }

    for (int kt = 0; kt < ntiles; kt++) {
        const int kbase = kt * BKT;

        // ---- store current K/V tile --------------------------------------------
        *reinterpret_cast<uint4*>(&Kh[lr][lc]) = kRegH;
        *reinterpret_cast<uint4*>(&Kl[lr][lc]) = kRegL;
        *reinterpret_cast<uint4*>(&Vh[lr][lc]) = vRegH;
        *reinterpret_cast<uint4*>(&Vl[lr][lc]) = vRegL;
        __syncthreads();   // b1

        // ---- prefetch next tile ------------------------------------------------
        if (kt + 1 < ntiles) {
            const size_t off = koff + (size_t)(kbase + BKT + lr) * DHc + lc;
            kRegH = *reinterpret_cast<const uint4*>(g_kh + off);
            kRegL = *reinterpret_cast<const uint4*>(g_kl + off);
            vRegH = *reinterpret_cast<const uint4*>(g_vh + off);
            vRegL = *reinterpret_cast<const uint4*>(g_vl + off);
        }

        // ---- S = Q K^T (bf16x3), each warp a 16x16 block -----------------------
        {
            wmma::fragment<wmma::accumulator, 16, 16, 16, float> accS;
            wmma::fill_fragment(accS, 0.0f);
#pragma unroll
            for (int kd = 0; kd < 4; kd++) {
                wmma::fragment<wmma::matrix_b, 16, 16, 16, __nv_bfloat16, wmma::col_major> fKh;
                wmma::fragment<wmma::matrix_b, 16, 16, 16, __nv_bfloat16, wmma::col_major> fKl;
                wmma::load_matrix_sync(fKh, &Kh[wc * 16][kd * 16], KP);
                wmma::load_matrix_sync(fKl, &Kl[wc * 16][kd * 16], KP);
                wmma::mma_sync(accS, fQh[kd], fKh, accS);
                wmma::mma_sync(accS, fQh[kd], fKl, accS);
                wmma::mma_sync(accS, fQl[kd], fKh, accS);
            }
            wmma::store_matrix_sync(&SsOs[wr * 16][wc * 16], accS, OP, wmma::mem_row_major);
        }
        __syncthreads();   // b2

        // ---- online softmax: 4 threads per row, 8 cols each --------------------
        {
            const int qi = qt * BQ + srow;
            const float mold = m_s[srow];
            float sv[8];
            float mmax = mold;
#pragma unroll
            for (int j = 0; j < 8; j++) {
                const int ccol = ssub * 8 + j;
                const float s = (kbase + ccol <= qi) ? SsOs[srow][ccol] * 0.125f : -1e30f;
                sv[j] = s;
                mmax = fmaxf(mmax, s);
            }
            mmax = fmaxf(mmax, __shfl_xor_sync(0xffffffffu, mmax, 1));
            mmax = fmaxf(mmax, __shfl_xor_sync(0xffffffffu, mmax, 2));
            float lsum = 0.f;
#pragma unroll
            for (int j = 0; j < 8; j++) {
                const float e = __expf(sv[j] - mmax);
                lsum += e;
                const __nv_bfloat16 eh = __float2bfloat16_rn(e);
                Ph[srow][ssub * 8 + j] = eh;
                Pl[srow][ssub * 8 + j] = __float2bfloat16_rn(e - __bfloat162float(eh));
            }
            lsum += __shfl_xor_sync(0xffffffffu, lsum, 1);
            lsum += __shfl_xor_sync(0xffffffffu, lsum, 2);
            if (ssub == 0) {
                const float cr = __expf(mold - mmax);
                m_s[srow]    = mmax;
                l_s[srow]    = l_s[srow] * cr + lsum;
                corr_s[srow] = cr;
            }
        }
        __syncthreads();   // b3

        // ---- O_tile = P V (bf16x3), each warp 16x32 ----------------------------
        {
            wmma::fragment<wmma::accumulator, 16, 16, 16, float> accO[2];
            wmma::fill_fragment(accO[0], 0.0f);
            wmma::fill_fragment(accO[1], 0.0f);
#pragma unroll
            for (int ks = 0; ks < 2; ks++) {
                wmma::fragment<wmma::matrix_a, 16, 16, 16, __nv_bfloat16, wmma::row_major> fPh;
                wmma::fragment<wmma::matrix_a, 16, 16, 16, __nv_bfloat16, wmma::row_major> fPl;
                wmma::load_matrix_sync(fPh, &Ph[wr * 16][ks * 16], PP);
                wmma::load_matrix_sync(fPl, &Pl[wr * 16][ks * 16], PP);
#pragma unroll
                for (int nj = 0; nj < 2; nj++) {
                    wmma::fragment<wmma::matrix_b, 16, 16, 16, __nv_bfloat16, wmma::row_major> fVh;
                    wmma::fragment<wmma::matrix_b, 16, 16, 16, __nv_bfloat16, wmma::row_major> fVl;
                    wmma::load_matrix_sync(fVh, &Vh[ks * 16][wc * 32 + nj * 16], KP);
                    wmma::load_matrix_sync(fVl, &Vl[ks * 16][wc * 32 + nj * 16], KP);
                    wmma::mma_sync(accO[nj], fPh, fVh, accO[nj]);
                    wmma::mma_sync(accO[nj], fPh, fVl, accO[nj]);
                    wmma::mma_sync(accO[nj], fPl, fVh, accO[nj]);
                }
            }
            wmma::store_matrix_sync(&SsOs[wr * 16][wc * 32],      accO[0], OP, wmma::mem_row_major);
            wmma::store_matrix_sync(&SsOs[wr * 16][wc * 32 + 16], accO[1], OP, wmma::mem_row_major);
        }
        __syncthreads();   // b4

        // ---- rescale + accumulate into register O ------------------------------
#pragma unroll
        for (int i = 0; i < 4; i++) {
            const float cr = corr_s[qr0 + i];
#pragma unroll
            for (int j = 0; j < 4; j++) {
                o[i][j] = o[i][j] * cr + SsOs[qr0 + i][dc0 + j];
            }
        }
        // no end barrier: next iteration writes Kh/Vh (disjoint from SsOs),
        // and next write to SsOs (S store) is after b1+b2.
    }

    // ---- normalize and write ctx[b][t][h*DH + d] -----------------------------
#pragma unroll
    for (int i = 0; i < 4; i++) {
        const float inv = 1.f / l_s[qr0 + i];
        const size_t off =
            (size_t)(b * Tc + qt * BQ + qr0 + i) * Dc + h * DHc + dc0;
        *reinterpret_cast<float4*>(g_ctx + off) =
            make_float4(o[i][0] * inv, o[i][1] * inv, o[i][2] * inv, o[i][3] * inv);
    }
}

// ---------------- launch ------------------------------------------------------
extern "C" void kernel_launch(void* const* d_in, const int* in_sizes, int n_in,
                              void* d_out, int out_size) {
    const float* x  = (const float*)d_in[0];
    const float* Wq = (const float*)d_in[1];
    const float* Wk = (const float*)d_in[2];
    const float* Wv = (const float*)d_in[3];
    const float* Wo = (const float*)d_in[4];
    float* out = (float*)d_out;

    // pre-split inputs and weights to bf16 hi/lo
    k_split_x <<<(BT * Dc)  / 1024, 256>>>(x);
    k_split_wq<<<(Dc * Dc)  / 1024, 256>>>(Wq);
    k_split_wk<<<(Dc * DKV) / 1024, 256>>>(Wk);
    k_split_wv<<<(Dc * DKV) / 1024, 256>>>(Wv);
    k_split_wo<<<(Dc * Dc)  / 1024, 256>>>(Wo);

    dim3 gridBig(Dc / 128, BT / 128);
    dim3 gridKV(DKV / 128, BT / 128);

    k_qproj<<<gridBig, 256>>>();
    k_kproj<<<gridKV, 256>>>();
    k_vproj<<<gridKV, 256>>>();

    rope_q_kernel<<<(BT * Dc) / 256, 256>>>();
    rope_k_kernel<<<(BT * DKV) / 256, 256>>>();
    k_split_v<<<(BT * DKV) / 1024, 256>>>();

    attn_kernel<<<dim3(Hc * Bc, Tc / 64), 256>>>();

    k_split_ctx<<<(BT * Dc) / 1024, 256>>>();
    k_oproj<<<gridBig, 256>>>(out);
}

// round 16
// speedup vs baseline: 1.1258x; 1.0003x over previous
#include <cuda_runtime.h>
#include <cuda_bf16.h>
#include <mma.h>
#include <math.h>

using namespace nvcuda;

// Problem constants
constexpr int Bc   = 2;
constexpr int Tc   = 2048;
constexpr int Dc   = 2048;
constexpr int Hc   = 32;
constexpr int HKVc = 8;
constexpr int DHc  = 64;
constexpr int BT   = Bc * Tc;          // 4096
constexpr int DKV  = HKVc * DHc;       // 512

// ---------------- scratch (__device__ globals, no allocation) ----------------
// NOTE: only ever referenced from DEVICE code (never passed from host).
__device__ float g_qraw[BT * Dc];
__device__ float g_kraw[BT * DKV];
__device__ float g_vraw[BT * DKV];
__device__ float g_ctx [BT * Dc];

// pre-split bf16 hi/lo operand buffers
__device__ __nv_bfloat16 g_xh [BT * Dc],  g_xl [BT * Dc];
__device__ __nv_bfloat16 g_wqh[Dc * Dc],  g_wql[Dc * Dc];
__device__ __nv_bfloat16 g_wkh[Dc * DKV], g_wkl[Dc * DKV];
__device__ __nv_bfloat16 g_wvh[Dc * DKV], g_wvl[Dc * DKV];
__device__ __nv_bfloat16 g_woh[Dc * Dc],  g_wol[Dc * Dc];
__device__ __nv_bfloat16 g_qh [BT * Dc],  g_ql [BT * Dc];   // [B,H,T,DH] roped
__device__ __nv_bfloat16 g_kh [BT * DKV], g_kl [BT * DKV];  // [B,HKV,T,DH] roped
__device__ __nv_bfloat16 g_vh [BT * DKV], g_vl [BT * DKV];  // [B,HKV,T,DH]
__device__ __nv_bfloat16 g_ctxh[BT * Dc], g_ctxl[BT * Dc];

// ---------------- helpers -----------------------------------------------------
// split 16 consecutive fp32 (given as 4 float4) into hi/lo bf16, vector stores.
// hi/lo must be 32B-aligned (element offset multiple of 16).
__device__ __forceinline__ void split16_store(const float4* v,
                                              __nv_bfloat16* hi,
                                              __nv_bfloat16* lo) {
    __nv_bfloat16 hv[16], lv[16];
#pragma unroll
    for (int j = 0; j < 4; j++) {
        const float a0 = v[j].x, a1 = v[j].y, a2 = v[j].z, a3 = v[j].w;
        const __nv_bfloat16 h0 = __float2bfloat16_rn(a0);
        const __nv_bfloat16 h1 = __float2bfloat16_rn(a1);
        const __nv_bfloat16 h2 = __float2bfloat16_rn(a2);
        const __nv_bfloat16 h3 = __float2bfloat16_rn(a3);
        hv[j * 4 + 0] = h0; hv[j * 4 + 1] = h1;
        hv[j * 4 + 2] = h2; hv[j * 4 + 3] = h3;
        lv[j * 4 + 0] = __float2bfloat16_rn(a0 - __bfloat162float(h0));
        lv[j * 4 + 1] = __float2bfloat16_rn(a1 - __bfloat162float(h1));
        lv[j * 4 + 2] = __float2bfloat16_rn(a2 - __bfloat162float(h2));
        lv[j * 4 + 3] = __float2bfloat16_rn(a3 - __bfloat162float(h3));
    }
#pragma unroll
    for (int j = 0; j < 16; j += 8) {
        *reinterpret_cast<uint4*>(hi + j) = *reinterpret_cast<const uint4*>(&hv[j]);
        *reinterpret_cast<uint4*>(lo + j) = *reinterpret_cast<const uint4*>(&lv[j]);
    }
}

// generic contiguous split: 16 elements (4 independent float4 loads) per thread
__device__ __forceinline__ void split_stream_body(const float* __restrict__ src,
                                                  __nv_bfloat16* __restrict__ hi,
                                                  __nv_bfloat16* __restrict__ lo) {
    const size_t i0 = ((size_t)blockIdx.x * 256 + threadIdx.x) * 4;  // float4 idx
    float4 v[4];
#pragma unroll
    for (int j = 0; j < 4; j++) {
        v[j] = reinterpret_cast<const float4*>(src)[i0 + j];
    }
    split16_store(v, hi + i0 * 4, lo + i0 * 4);
}

// ---------------- elementwise split kernels -----------------------------------
__global__ __launch_bounds__(256) void k_split_x(const float* __restrict__ src) {
    split_stream_body(src, g_xh, g_xl);
}
__global__ __launch_bounds__(256) void k_split_wq(const float* __restrict__ src) {
    split_stream_body(src, g_wqh, g_wql);
}
__global__ __launch_bounds__(256) void k_split_wk(const float* __restrict__ src) {
    split_stream_body(src, g_wkh, g_wkl);
}
__global__ __launch_bounds__(256) void k_split_wv(const float* __restrict__ src) {
    split_stream_body(src, g_wvh, g_wvl);
}
__global__ __launch_bounds__(256) void k_split_wo(const float* __restrict__ src) {
    split_stream_body(src, g_woh, g_wol);
}
__global__ __launch_bounds__(256) void k_split_ctx() {
    split_stream_body(g_ctx, g_ctxh, g_ctxl);
}
// V: [B,T,HKV*DH] -> [B,HKV,T,DH], split to hi/lo; 16 elements per thread
__global__ __launch_bounds__(256) void k_split_v() {
    const int e  = (blockIdx.x * 256 + threadIdx.x) * 16;   // 16-aligned elem idx
    const int d  = e & 63;            // 16-aligned, 0/16/32/48
    const int t  = (e >> 6) & 2047;
    const int kv = (e >> 17) & 7;
    const int b  = e >> 20;
    const float* src = g_vraw + (size_t)(b * Tc + t) * DKV + kv * DHc + d;
    float4 v[4];
#pragma unroll
    for (int j = 0; j < 4; j++) {
        v[j] = *reinterpret_cast<const float4*>(src + j * 4);
    }
    split16_store(v, g_vh + e, g_vl + e);
}

// ---------------- RoPE (vectorized 16 elems/thread, fused hi/lo split) --------
#define ROPE_LN_C 0.28782313662425575f

__global__ __launch_bounds__(256) void rope_q_kernel() {
    const int base = (blockIdx.x * 256 + threadIdx.x) * 16;   // over [B,H,T,DH]
    const int d = base & 63;          // 16-aligned -> uniform half for 16 elems
    const int t = (base >> 6) & 2047;
    const int h = (base >> 17) & 31;
    const int b = base >> 22;
    const size_t row = (size_t)(b * Tc + t) * Dc + h * DHc;
    const int   pd  = (d < 32) ? d + 32 : d - 32;
    const float sgn = (d < 32) ? -1.f : 1.f;

    float raw[16], pr[16];
#pragma unroll
    for (int j = 0; j < 16; j += 4) {
        *reinterpret_cast<float4*>(&raw[j]) =
            *reinterpret_cast<const float4*>(g_qraw + row + d + j);
        *reinterpret_cast<float4*>(&pr[j]) =
            *reinterpret_cast<const float4*>(g_qraw + row + pd + j);
    }
    __nv_bfloat16 hv[16], lv[16];
#pragma unroll
    for (int j = 0; j < 16; j++) {
        const int   i    = (d & 31) + j;
        const float invf = expf(-(float)i * ROPE_LN_C);
        const float ang  = (float)t * invf;
        const float rot  = sgn * pr[j];
        const float val  = raw[j] * cosf(ang) + rot * sinf(ang);
        const __nv_bfloat16 hi = __float2bfloat16_rn(val);
        hv[j] = hi;
        lv[j] = __float2bfloat16_rn(val - __bfloat162float(hi));
    }
#pragma unroll
    for (int j = 0; j < 16; j += 8) {
        *reinterpret_cast<uint4*>(g_qh + base + j) = *reinterpret_cast<const uint4*>(&hv[j]);
        *reinterpret_cast<uint4*>(g_ql + base + j) = *reinterpret_cast<const uint4*>(&lv[j]);
    }
}

__global__ __launch_bounds__(256) void rope_k_kernel() {
    const int base = (blockIdx.x * 256 + threadIdx.x) * 16;   // over [B,HKV,T,DH]
    const int d  = base & 63;
    const int t  = (base >> 6) & 2047;
    const int kv = (base >> 17) & 7;
    const int b  = base >> 20;
    const size_t row = (size_t)(b * Tc + t) * DKV + kv * DHc;
    const int   pd  = (d < 32) ? d + 32 : d - 32;
    const float sgn = (d < 32) ? -1.f : 1.f;

    float raw[16], pr[16];
#pragma unroll
    for (int j = 0; j < 16; j += 4) {
        *reinterpret_cast<float4*>(&raw[j]) =
            *reinterpret_cast<const float4*>(g_kraw + row + d + j);
        *reinterpret_cast<float4*>(&pr[j]) =
            *reinterpret_cast<const float4*>(g_kraw + row + pd + j);
    }
    __nv_bfloat16 hv[16], lv[16];
#pragma unroll
    for (int j = 0; j < 16; j++) {
        const int   i    = (d & 31) + j;
        const float invf = expf(-(float)i * ROPE_LN_C);
        const float ang  = (float)t * invf;
        const float rot  = sgn * pr[j];
        const float val  = raw[j] * cosf(ang) + rot * sinf(ang);
        const __nv_bfloat16 hi = __float2bfloat16_rn(val);
        hv[j] = hi;
        lv[j] = __float2bfloat16_rn(val - __bfloat162float(hi));
    }
#pragma unroll
    for (int j = 0; j < 16; j += 8) {
        *reinterpret_cast<uint4*>(g_kh + base + j) = *reinterpret_cast<const uint4*>(&hv[j]);
        *reinterpret_cast<uint4*>(g_kl + base + j) = *reinterpret_cast<const uint4*>(&lv[j]);
    }
}

// ---------------- pure bf16 GEMM via wmma (device body) ----------------------
// C[4096, N] = (Ah+Al)[4096, 2048] @ (Bh+Bl)[2048, N]  (bf16x3: drops Al*Bl)
// block = 256 (8 warps: 4 along M x 2 along N), CTA tile 128x128, BK=32.
template <int N>
__device__ __forceinline__ void bf16_gemm_body(const __nv_bfloat16* __restrict__ Ahg,
                                               const __nv_bfloat16* __restrict__ Alg,
                                               const __nv_bfloat16* __restrict__ Bhg,
                                               const __nv_bfloat16* __restrict__ Blg,
                                               float* __restrict__ C) {
    constexpr int K  = 2048;
    constexpr int BM = 128, BN = 128, BK = 32;
    constexpr int ASTR = BK + 8;   // 40 bf16 = 80 B per row
    constexpr int BSTR = BN + 8;   // 136 bf16 = 272 B per row

    __shared__ __align__(32) __nv_bfloat16 Ah[BM][ASTR];
    __shared__ __align__(32) __nv_bfloat16 Al[BM][ASTR];
    __shared__ __align__(32) __nv_bfloat16 Bh[BK][BSTR];
    __shared__ __align__(32) __nv_bfloat16 Bl[BK][BSTR];

    const int tid  = threadIdx.x;
    const int warp = tid >> 5;
    const int wm   = (warp >> 1) * 32;
    const int wn   = (warp & 1) * 64;
    const int brow = blockIdx.y * BM;
    const int bcol = blockIdx.x * BN;

    const int ar0 = tid >> 2;              // row of first A vec (0..63)
    const int ac  = (tid & 3) * 8;         // col (bf16 units)
    const int br0 = tid >> 4;              // row of first B vec (0..15)
    const int bc  = (tid & 15) * 8;

    wmma::fragment<wmma::accumulator, 16, 16, 16, float> acc[2][4];
#pragma unroll
    for (int mi = 0; mi < 2; mi++) {
#pragma unroll
        for (int nj = 0; nj < 4; nj++) {
            wmma::fill_fragment(acc[mi][nj], 0.0f);
        }
    }

    uint4 ahR[2], alR[2], bhR[2], blR[2];
#pragma unroll
    for (int j = 0; j < 2; j++) {
        const size_t aoff = (size_t)(brow + ar0 + j * 64) * K + ac;
        ahR[j] = *reinterpret_cast<const uint4*>(Ahg + aoff);
        alR[j] = *reinterpret_cast<const uint4*>(Alg + aoff);
        const size_t boff = (size_t)(br0 + j * 16) * N + bcol + bc;
        bhR[j] = *reinterpret_cast<const uint4*>(Bhg + boff);
        blR[j] = *reinterpret_cast<const uint4*>(Blg + boff);
    }

    for (int kt = 0; kt < K / BK; kt++) {
#pragma unroll
        for (int j = 0; j < 2; j++) {
            *reinterpret_cast<uint4*>(&Ah[ar0 + j * 64][ac]) = ahR[j];
            *reinterpret_cast<uint4*>(&Al[ar0 + j * 64][ac]) = alR[j];
            *reinterpret_cast<uint4*>(&Bh[br0 + j * 16][bc]) = bhR[j];
            *reinterpret_cast<uint4*>(&Bl[br0 + j * 16][bc]) = blR[j];
        }
        __syncthreads();

        if (kt + 1 < K / BK) {
            const int k0 = (kt + 1) * BK;
#pragma unroll
            for (int j = 0; j < 2; j++) {
                const size_t aoff = (size_t)(brow + ar0 + j * 64) * K + k0 + ac;
                ahR[j] = *reinterpret_cast<const uint4*>(Ahg + aoff);
                alR[j] = *reinterpret_cast<const uint4*>(Alg + aoff);
                const size_t boff = (size_t)(k0 + br0 + j * 16) * N + bcol + bc;
                bhR[j] = *reinterpret_cast<const uint4*>(Bhg + boff);
                blR[j] = *reinterpret_cast<const uint4*>(Blg + boff);
            }
        }

#pragma unroll
        for (int ks = 0; ks < 2; ks++) {
            wmma::fragment<wmma::matrix_a, 16, 16, 16, __nv_bfloat16, wmma::row_major> fAh[2];
            wmma::fragment<wmma::matrix_a, 16, 16, 16, __nv_bfloat16, wmma::row_major> fAl[2];
#pragma unroll
            for (int mi = 0; mi < 2; mi++) {
                wmma::load_matrix_sync(fAh[mi], &Ah[wm + mi * 16][ks * 16], ASTR);
                wmma::load_matrix_sync(fAl[mi], &Al[wm + mi * 16][ks * 16], ASTR);
            }
#pragma unroll
            for (int nj = 0; nj < 4; nj++) {
                wmma::fragment<wmma::matrix_b, 16, 16, 16, __nv_bfloat16, wmma::row_major> fBh;
                wmma::fragment<wmma::matrix_b, 16, 16, 16, __nv_bfloat16, wmma::row_major> fBl;
                wmma::load_matrix_sync(fBh, &Bh[ks * 16][wn + nj * 16], BSTR);
                wmma::load_matrix_sync(fBl, &Bl[ks * 16][wn + nj * 16], BSTR);
#pragma unroll
                for (int mi = 0; mi < 2; mi++) {
                    wmma::mma_sync(acc[mi][nj], fAh[mi], fBh, acc[mi][nj]);
                    wmma::mma_sync(acc[mi][nj], fAh[mi], fBl, acc[mi][nj]);
                    wmma::mma_sync(acc[mi][nj], fAl[mi], fBh, acc[mi][nj]);
                }
            }
        }
        __syncthreads();
    }

#pragma unroll
    for (int mi = 0; mi < 2; mi++) {
#pragma unroll
        for (int nj = 0; nj < 4; nj++) {
            float* p = C + (size_t)(brow + wm + mi * 16) * N + bcol + wn + nj * 16;
            wmma::store_matrix_sync(p, acc[mi][nj], N, wmma::mem_row_major);
        }
    }
}

// Wrappers: scratch globals referenced from DEVICE code only.
__global__ __launch_bounds__(256) void k_qproj() {
    bf16_gemm_body<Dc>(g_xh, g_xl, g_wqh, g_wql, g_qraw);
}
__global__ __launch_bounds__(256) void k_kproj() {
    bf16_gemm_body<DKV>(g_xh, g_xl, g_wkh, g_wkl, g_kraw);
}
__global__ __launch_bounds__(256) void k_vproj() {
    bf16_gemm_body<DKV>(g_xh, g_xl, g_wvh, g_wvl, g_vraw);
}
__global__ __launch_bounds__(256) void k_oproj(float* __restrict__ out) {
    bf16_gemm_body<Dc>(g_ctxh, g_ctxl, g_woh, g_wol, out);
}

// ---------------- Causal flash attention (bf16x3 wmma, parallel softmax) -----
// grid: (H*B, T/64) with LPT order: qt = T/64-1 - blockIdx.y (longest first).
// block: 256 (8 warps: 4 along q x 2 along key/dh)
__global__ __launch_bounds__(256) void attn_kernel() {
    constexpr int BQ  = 64;
    constexpr int BKT = 32;
    constexpr int KP  = 72;   // bf16 row stride for K/V/Q-staging
    constexpr int PP  = 40;   // bf16 row stride for P
    constexpr int OP  = 72;   // fp32 row stride for Ss/Os

    __shared__ __align__(32) __nv_bfloat16 Kh[BKT][KP];
    __shared__ __align__(32) __nv_bfloat16 Kl[BKT][KP];
    __shared__ __align__(32) __nv_bfloat16 Vh[BKT][KP];
    __shared__ __align__(32) __nv_bfloat16 Vl[BKT][KP];
    __shared__ __align__(32) __nv_bfloat16 Ph[BQ][PP];
    __shared__ __align__(32) __nv_bfloat16 Pl[BQ][PP];
    __shared__ __align__(32) float SsOs[BQ][OP];   // Q staging, S tile, O tile
    __shared__ float m_s[BQ], l_s[BQ], corr_s[BQ];

    const int tid  = threadIdx.x;
    const int warp = tid >> 5;
    const int wr   = warp >> 1;    // 0..3: 16-row group of q
    const int wc   = warp & 1;     // 0..1: 16-col group (S) / 32-col group (O)
    const int h    = blockIdx.x & 31;
    const int b    = blockIdx.x >> 5;
    const int qt   = (Tc / 64 - 1) - blockIdx.y;   // LPT: longest jobs first
    const int kv   = h >> 2;

    const size_t qoff = ((size_t)(b * Hc + h) * Tc + qt * BQ) * DHc;
    const size_t koff = (size_t)(b * HKVc + kv) * Tc * DHc;

    // ---- stage Q hi/lo (bf16) into SsOs region, then load fragments ----------
    __nv_bfloat16* Qhs = reinterpret_cast<__nv_bfloat16*>(&SsOs[0][0]);
    __nv_bfloat16* Qls = Qhs + BQ * KP;
#pragma unroll
    for (int j = 0; j < 2; j++) {
        const int i = tid + j * 256;            // 512 uint4 total (64x64 bf16)
        const int r = i >> 3;
        const int c = (i & 7) * 8;
        *reinterpret_cast<uint4*>(Qhs + r * KP + c) =
            *reinterpret_cast<const uint4*>(g_qh + qoff + (size_t)r * DHc + c);
        *reinterpret_cast<uint4*>(Qls + r * KP + c) =
            *reinterpret_cast<const uint4*>(g_ql + qoff + (size_t)r * DHc + c);
    }
    if (tid < BQ) { m_s[tid] = -1e30f; l_s[tid] = 0.f; }
    __syncthreads();

    wmma::fragment<wmma::matrix_a, 16, 16, 16, __nv_bfloat16, wmma::row_major> fQh[4];
    wmma::fragment<wmma::matrix_a, 16, 16, 16, __nv_bfloat16, wmma::row_major> fQl[4];
#pragma unroll
    for (int kd = 0; kd < 4; kd++) {
        wmma::load_matrix_sync(fQh[kd], Qhs + (wr * 16) * KP + kd * 16, KP);
        wmma::load_matrix_sync(fQl[kd], Qls + (wr * 16) * KP + kd * 16, KP);
    }
    __syncthreads();   // Q staging region is reused as S/O below

    float o[4][4];
#pragma unroll
    for (int i = 0; i < 4; i++) {
#pragma unroll
        for (int j = 0; j < 4; j++) { o[i][j] = 0.f; }
    }
    const int qr0  = (tid >> 4) * 4;   // output rows
    const int dc0  = (tid & 15) * 4;   // output cols
    const int srow = tid >> 2;         // softmax row (4 threads per row)
    const int ssub = tid & 3;          // softmax sub-column group (8 cols)
    const int ntiles = 2 * qt + 2;

    // K/V tile loads: 32x64 bf16 = 256 uint4 per array, 1 per thread
    const int lr = tid >> 3;           // 0..31
    const int lc = (tid & 7) * 8;      // 0..56

    uint4 kRegH, kRegL, vRegH, vRegL;
    {
        const size_t off = koff + (size_t)lr * DHc + lc;
        kRegH = *reinterpret_cast<const uint4*>(g_kh + off);
        kRegL = *reinterpret_cast<const uint4*>(g_kl + off);
        vRegH = *reinterpret_cast<const uint4*>(g_vh + off);
        vRegL = *reinterpret_cast<const uint4*>(g_vl + off);
    }

    for (int kt = 0; kt < ntiles; kt++) {
        const int kbase = kt * BKT;

        // ---- store current K/V tile --------------------------------------------
        *reinterpret_cast<uint4*>(&Kh[lr][lc]) = kRegH;
        *reinterpret_cast<uint4*>(&Kl[lr][lc]) = kRegL;
        *reinterpret_cast<uint4*>(&Vh[lr][lc]) = vRegH;
        *reinterpret_cast<uint4*>(&Vl[lr][lc]) = vRegL;
        __syncthreads();   // b1

        // ---- prefetch next tile ------------------------------------------------
        if (kt + 1 < ntiles) {
            const size_t off = koff + (size_t)(kbase + BKT + lr) * DHc + lc;
            kRegH = *reinterpret_cast<const uint4*>(g_kh + off);
            kRegL = *reinterpret_cast<const uint4*>(g_kl + off);
            vRegH = *reinterpret_cast<const uint4*>(g_vh + off);
            vRegL = *reinterpret_cast<const uint4*>(g_vl + off);
        }

        // ---- S = Q K^T (bf16x3), each warp a 16x16 block -----------------------
        {
            wmma::fragment<wmma::accumulator, 16, 16, 16, float> accS;
            wmma::fill_fragment(accS, 0.0f);
#pragma unroll
            for (int kd = 0; kd < 4; kd++) {
                wmma::fragment<wmma::matrix_b, 16, 16, 16, __nv_bfloat16, wmma::col_major> fKh;
                wmma::fragment<wmma::matrix_b, 16, 16, 16, __nv_bfloat16, wmma::col_major> fKl;
                wmma::load_matrix_sync(fKh, &Kh[wc * 16][kd * 16], KP);
                wmma::load_matrix_sync(fKl, &Kl[wc * 16][kd * 16], KP);
                wmma::mma_sync(accS, fQh[kd], fKh, accS);
                wmma::mma_sync(accS, fQh[kd], fKl, accS);
                wmma::mma_sync(accS, fQl[kd], fKh, accS);
            }
            wmma::store_matrix_sync(&SsOs[wr * 16][wc * 16], accS, OP, wmma::mem_row_major);
        }
        __syncthreads();   // b2

        // ---- online softmax: 4 threads per row, 8 cols each --------------------
        {
            const int qi = qt * BQ + srow;
            const float mold = m_s[srow];
            float sv[8];
            float mmax = mold;
#pragma unroll
            for (int j = 0; j < 8; j++) {
                const int ccol = ssub * 8 + j;
                const float s = (kbase + ccol <= qi) ? SsOs[srow][ccol] * 0.125f : -1e30f;
                sv[j] = s;
                mmax = fmaxf(mmax, s);
            }
            mmax = fmaxf(mmax, __shfl_xor_sync(0xffffffffu, mmax, 1));
            mmax = fmaxf(mmax, __shfl_xor_sync(0xffffffffu, mmax, 2));
            float lsum = 0.f;
#pragma unroll
            for (int j = 0; j < 8; j++) {
                const float e = __expf(sv[j] - mmax);
                lsum += e;
                const __nv_bfloat16 eh = __float2bfloat16_rn(e);
                Ph[srow][ssub * 8 + j] = eh;
                Pl[srow][ssub * 8 + j] = __float2bfloat16_rn(e - __bfloat162float(eh));
            }
            lsum += __shfl_xor_sync(0xffffffffu, lsum, 1);
            lsum += __shfl_xor_sync(0xffffffffu, lsum, 2);
            if (ssub == 0) {
                const float cr = __expf(mold - mmax);
                m_s[srow]    = mmax;
                l_s[srow]    = l_s[srow] * cr + lsum;
                corr_s[srow] = cr;
            }
        }
        __syncthreads();   // b3

        // ---- O_tile = P V (bf16x3), each warp 16x32 ----------------------------
        {
            wmma::fragment<wmma::accumulator, 16, 16, 16, float> accO[2];
            wmma::fill_fragment(accO[0], 0.0f);
            wmma::fill_fragment(accO[1], 0.0f);
#pragma unroll
            for (int ks = 0; ks < 2; ks++) {
                wmma::fragment<wmma::matrix_a, 16, 16, 16, __nv_bfloat16, wmma::row_major> fPh;
                wmma::fragment<wmma::matrix_a, 16, 16, 16, __nv_bfloat16, wmma::row_major> fPl;
                wmma::load_matrix_sync(fPh, &Ph[wr * 16][ks * 16], PP);
                wmma::load_matrix_sync(fPl, &Pl[wr * 16][ks * 16], PP);
#pragma unroll
                for (int nj = 0; nj < 2; nj++) {
                    wmma::fragment<wmma::matrix_b, 16, 16, 16, __nv_bfloat16, wmma::row_major> fVh;
                    wmma::fragment<wmma::matrix_b, 16, 16, 16, __nv_bfloat16, wmma::row_major> fVl;
                    wmma::load_matrix_sync(fVh, &Vh[ks * 16][wc * 32 + nj * 16], KP);
                    wmma::load_matrix_sync(fVl, &Vl[ks * 16][wc * 32 + nj * 16], KP);
                    wmma::mma_sync(accO[nj], fPh, fVh, accO[nj]);
                    wmma::mma_sync(accO[nj], fPh, fVl, accO[nj]);
                    wmma::mma_sync(accO[nj], fPl, fVh, accO[nj]);
                }
            }
            wmma::store_matrix_sync(&SsOs[wr * 16][wc * 32],      accO[0], OP, wmma::mem_row_major);
            wmma::store_matrix_sync(&SsOs[wr * 16][wc * 32 + 16], accO[1], OP, wmma::mem_row_major);
        }
        __syncthreads();   // b4

        // ---- rescale + accumulate into register O ------------------------------
#pragma unroll
        for (int i = 0; i < 4; i++) {
            const float cr = corr_s[qr0 + i];
#pragma unroll
            for (int j = 0; j < 4; j++) {
                o[i][j] = o[i][j] * cr + SsOs[qr0 + i][dc0 + j];
            }
        }
        // no end barrier: next iteration writes Kh/Vh (disjoint from SsOs),
        // and next write to SsOs (S store) is after b1+b2.
    }

    // ---- normalize and write ctx[b][t][h*DH + d] -----------------------------
#pragma unroll
    for (int i = 0; i < 4; i++) {
        const float inv = 1.f / l_s[qr0 + i];
        const size_t off =
            (size_t)(b * Tc + qt * BQ + qr0 + i) * Dc + h * DHc + dc0;
        *reinterpret_cast<float4*>(g_ctx + off) =
            make_float4(o[i][0] * inv, o[i][1] * inv, o[i][2] * inv, o[i][3] * inv);
    }
}

// ---------------- launch ------------------------------------------------------
extern "C" void kernel_launch(void* const* d_in, const int* in_sizes, int n_in,
                              void* d_out, int out_size) {
    const float* x  = (const float*)d_in[0];
    const float* Wq = (const float*)d_in[1];
    const float* Wk = (const float*)d_in[2];
    const float* Wv = (const float*)d_in[3];
    const float* Wo = (const float*)d_in[4];
    float* out = (float*)d_out;

    // pre-split inputs and weights to bf16 hi/lo (16 elems/thread)
    k_split_x <<<(BT * Dc)  / 4096, 256>>>(x);
    k_split_wq<<<(Dc * Dc)  / 4096, 256>>>(Wq);
    k_split_wk<<<(Dc * DKV) / 4096, 256>>>(Wk);
    k_split_wv<<<(Dc * DKV) / 4096, 256>>>(Wv);
    k_split_wo<<<(Dc * Dc)  / 4096, 256>>>(Wo);

    dim3 gridBig(Dc / 128, BT / 128);
    dim3 gridKV(DKV / 128, BT / 128);

    k_qproj<<<gridBig, 256>>>();
    k_kproj<<<gridKV, 256>>>();
    k_vproj<<<gridKV, 256>>>();

    rope_q_kernel<<<(BT * Dc)  / 4096, 256>>>();
    rope_k_kernel<<<(BT * DKV) / 4096, 256>>>();
    k_split_v<<<(BT * DKV) / 4096, 256>>>();

    attn_kernel<<<dim3(Hc * Bc, Tc / 64), 256>>>();

    k_split_ctx<<<(BT * Dc) / 4096, 256>>>();
    k_oproj<<<gridBig, 256>>>(out);
}